// round 7
// baseline (speedup 1.0000x reference)
#include <cuda_runtime.h>
#include <cuda_bf16.h>
#include <math.h>
#include <stdint.h>

#define B_ 8
#define T_ 2048
#define C_ 1024
#define H_ 64

// Q/K post-RoPE, bf16 hi/lo, row-major [B*T][64]
__device__ __align__(16) __nv_bfloat16 g_Qhi[B_*T_*H_];
__device__ __align__(16) __nv_bfloat16 g_Qlo[B_*T_*H_];
__device__ __align__(16) __nv_bfloat16 g_Khi[B_*T_*H_];
__device__ __align__(16) __nv_bfloat16 g_Klo[B_*T_*H_];
// V transposed [B][64 h][T], bf16 hi/lo
__device__ __align__(16) __nv_bfloat16 g_VThi[B_*H_*T_];
__device__ __align__(16) __nv_bfloat16 g_VTlo[B_*H_*T_];
// W split bf16 hi/lo, K-major [192][1024]
__device__ __align__(16) __nv_bfloat16 g_Bhi[192*1024];
__device__ __align__(16) __nv_bfloat16 g_Blo[192*1024];

__device__ __forceinline__ uint32_t smem_u32(const void* p) {
    uint32_t a;
    asm("{ .reg .u64 t; cvta.to.shared.u64 t, %1; cvt.u32.u64 %0, t; }" : "=r"(a) : "l"(p));
    return a;
}
__device__ __forceinline__ void ldmx4(uint32_t& r0, uint32_t& r1, uint32_t& r2, uint32_t& r3,
                                      uint32_t addr) {
    asm volatile("ldmatrix.sync.aligned.m8n8.x4.shared.b16 {%0,%1,%2,%3}, [%4];"
                 : "=r"(r0), "=r"(r1), "=r"(r2), "=r"(r3) : "r"(addr));
}
__device__ __forceinline__ void mma16816(float* c,
                                         uint32_t a0, uint32_t a1, uint32_t a2, uint32_t a3,
                                         uint32_t b0, uint32_t b1) {
    asm volatile("mma.sync.aligned.m16n8k16.row.col.f32.bf16.bf16.f32 "
                 "{%0,%1,%2,%3}, {%4,%5,%6,%7}, {%8,%9}, {%0,%1,%2,%3};"
                 : "+f"(c[0]), "+f"(c[1]), "+f"(c[2]), "+f"(c[3])
                 : "r"(a0), "r"(a1), "r"(a2), "r"(a3), "r"(b0), "r"(b1));
}
__device__ __forceinline__ uint32_t bf16x2(float a, float b) {
    __nv_bfloat16 h0 = __float2bfloat16(a), h1 = __float2bfloat16(b);
    return (uint32_t)__bfloat16_as_ushort(h0) | ((uint32_t)__bfloat16_as_ushort(h1) << 16);
}
__device__ __forceinline__ float bf16lo_res(float v) {
    return v - __bfloat162float(__float2bfloat16(v));
}
#define CP_A16(dst, src) \
    asm volatile("cp.async.cg.shared.global [%0], [%1], 16;" :: "r"(dst), "l"(src))
#define CP_COMMIT() asm volatile("cp.async.commit_group;" ::: "memory")
#define CP_WAIT0()  asm volatile("cp.async.wait_group 0;" ::: "memory")
#define CP_WAIT1()  asm volatile("cp.async.wait_group 1;" ::: "memory")

// ---------------------------------------------------------------------------
// Prep: split W{q,k,v} into bf16 hi/lo, K-major [192][1024]
// ---------------------------------------------------------------------------
__global__ __launch_bounds__(256) void prep_B_kernel(
    const float* __restrict__ Wq, const float* __restrict__ Wk, const float* __restrict__ Wv)
{
    int idx = blockIdx.x * 256 + threadIdx.x;
    int n = idx >> 10, k = idx & 1023;
    const float* W = (n < 64) ? Wq : (n < 128) ? Wk : Wv;
    float v = W[k * 64 + (n & 63)];
    __nv_bfloat16 h = __float2bfloat16(v);
    g_Bhi[idx] = h;
    g_Blo[idx] = __float2bfloat16(v - __bfloat162float(h));
}

// ---------------------------------------------------------------------------
// Projection GEMM (HMMA bf16 hi/lo split). M=128 x N=192 per CTA, 16 warps.
// ---------------------------------------------------------------------------
#define PA_STR 72
#define SM_AHI 0
#define SM_ALO (128*PA_STR*2)
#define SM_BHI (2*128*PA_STR*2)
#define SM_BLO (SM_BHI + 192*PA_STR*2)
#define SM_TOT (SM_BLO + 192*PA_STR*2)

__global__ __launch_bounds__(512) void proj_gemm_kernel(const float* __restrict__ x)
{
    extern __shared__ char smem[];
    const uint32_t sbase = smem_u32(smem);
    const int tid    = threadIdx.x;
    const int wid    = tid >> 5;
    const int lane   = tid & 31;
    const int warp_m = wid >> 2;
    const int warp_n = wid & 3;
    const int m0     = blockIdx.x * 128;

    uint32_t aOff[2], bOff[3];
    {
        int mlo = (lane >> 3) & 1, khi = (lane >> 4) & 1, r8 = lane & 7;
        #pragma unroll
        for (int mt = 0; mt < 2; mt++)
            aOff[mt] = (uint32_t)((warp_m*32 + mt*16 + mlo*8 + r8) * (PA_STR*2) + khi*16);
        #pragma unroll
        for (int p = 0; p < 3; p++)
            bOff[p] = (uint32_t)((warp_n*48 + p*16 + khi*8 + r8) * (PA_STR*2) + mlo*16);
    }

    float acc[2][6][4];
    #pragma unroll
    for (int mt = 0; mt < 2; mt++)
        #pragma unroll
        for (int nt = 0; nt < 6; nt++)
            #pragma unroll
            for (int q = 0; q < 4; q++) acc[mt][nt][q] = 0.f;

    #pragma unroll 1
    for (int c = 0; c < 16; c++) {
        const int kc = c * 64;
        if (c > 0) __syncthreads();

        #pragma unroll
        for (int it = tid; it < 2048; it += 512) {
            int r = it >> 4, q = it & 15;
            float4 f = *reinterpret_cast<const float4*>(x + (size_t)(m0 + r) * C_ + kc + q*4);
            uint32_t h0 = bf16x2(f.x, f.y), h1 = bf16x2(f.z, f.w);
            uint32_t l0 = bf16x2(bf16lo_res(f.x), bf16lo_res(f.y));
            uint32_t l1 = bf16x2(bf16lo_res(f.z), bf16lo_res(f.w));
            uint32_t off = (uint32_t)(r * (PA_STR*2) + q * 8);
            *reinterpret_cast<uint2*>(smem + SM_AHI + off) = make_uint2(h0, h1);
            *reinterpret_cast<uint2*>(smem + SM_ALO + off) = make_uint2(l0, l1);
        }
        #pragma unroll
        for (int it = tid; it < 1536; it += 512) {
            int n = it >> 3, s = it & 7;
            uint32_t off = (uint32_t)(n * (PA_STR*2) + s * 16);
            *reinterpret_cast<uint4*>(smem + SM_BHI + off) =
                *reinterpret_cast<const uint4*>(g_Bhi + (size_t)n * 1024 + kc + s*8);
            *reinterpret_cast<uint4*>(smem + SM_BLO + off) =
                *reinterpret_cast<const uint4*>(g_Blo + (size_t)n * 1024 + kc + s*8);
        }
        __syncthreads();

        #pragma unroll 1
        for (int pass = 0; pass < 3; pass++) {
            uint32_t aBase = sbase + ((pass < 2) ? SM_AHI : SM_ALO);
            uint32_t bBase = sbase + ((pass == 1) ? SM_BLO : SM_BHI);
            #pragma unroll
            for (int ks = 0; ks < 4; ks++) {
                uint32_t kb = (uint32_t)(ks * 32);
                uint32_t a[2][4];
                #pragma unroll
                for (int mt = 0; mt < 2; mt++)
                    ldmx4(a[mt][0], a[mt][1], a[mt][2], a[mt][3], aBase + aOff[mt] + kb);
                uint32_t b[6][2];
                #pragma unroll
                for (int p = 0; p < 3; p++) {
                    uint32_t r0, r1, r2, r3;
                    ldmx4(r0, r1, r2, r3, bBase + bOff[p] + kb);
                    b[p*2][0] = r0; b[p*2][1] = r1;
                    b[p*2+1][0] = r2; b[p*2+1][1] = r3;
                }
                #pragma unroll
                for (int mt = 0; mt < 2; mt++)
                    #pragma unroll
                    for (int nt = 0; nt < 6; nt++)
                        mma16816(acc[mt][nt], a[mt][0], a[mt][1], a[mt][2], a[mt][3],
                                 b[nt][0], b[nt][1]);
            }
        }
    }

    const int g  = lane >> 2;
    const int tq = lane & 3;
    #pragma unroll
    for (int mt = 0; mt < 2; mt++) {
        int row0 = m0 + warp_m*32 + mt*16 + g;
        int rows[2] = { row0, row0 + 8 };
        #pragma unroll
        for (int nt = 0; nt < 6; nt++) {
            int col = warp_n*48 + nt*8 + 2*tq;
            int mat = col >> 6;
            int col_in = col & 63;
            if (mat < 2) {
                __nv_bfloat16* dhi = (mat == 0) ? g_Qhi : g_Khi;
                __nv_bfloat16* dlo = (mat == 0) ? g_Qlo : g_Klo;
                int pi = col_in >> 1;
                float inv = powf(10000.f, -(float)pi * (1.f / 32.f));
                #pragma unroll
                for (int rg = 0; rg < 2; rg++) {
                    int t = rows[rg] & (T_ - 1);
                    float sn, cs;
                    sincosf((float)t * inv, &sn, &cs);
                    float a0 = acc[mt][nt][rg*2], a1 = acc[mt][nt][rg*2 + 1];
                    float v0 = a0*cs - a1*sn, v1 = a1*cs + a0*sn;
                    size_t base = (size_t)rows[rg] * H_ + col_in;
                    *reinterpret_cast<uint32_t*>(&dhi[base]) = bf16x2(v0, v1);
                    *reinterpret_cast<uint32_t*>(&dlo[base]) = bf16x2(bf16lo_res(v0), bf16lo_res(v1));
                }
            } else {
                #pragma unroll
                for (int rg = 0; rg < 2; rg++) {
                    int bb = rows[rg] >> 11, tt = rows[rg] & (T_ - 1);
                    #pragma unroll
                    for (int e = 0; e < 2; e++) {
                        float v = acc[mt][nt][rg*2 + e];
                        size_t idx = ((size_t)bb * H_ + (col_in + e)) * T_ + tt;
                        g_VThi[idx] = __float2bfloat16(v);
                        g_VTlo[idx] = __float2bfloat16(bf16lo_res(v));
                    }
                }
            }
        }
    }
}

// ---------------------------------------------------------------------------
// Attention, 8 warps: warps (rw, ch) with rw = row group (16 q rows),
// ch = KV-column half (32 of 64 kv positions). Partner warps (w ^ 4) share
// rows; softmax max/sum merged through smem each iteration; PV partials
// (split over the kv reduction dim) merged once per pass.
// cp.async double-buffered K/V staging. CTA pairs (qt, 31-qt): 33 iters.
// ---------------------------------------------------------------------------
#define ASTR   72
#define TILE_B (64*ASTR*2)          // 9216 bytes per 64x64 bf16 tile
#define AQHI   0
#define AQLO   TILE_B
#define AKV0   (2*TILE_B)           // buffer 0: KHI,KLO,VHI,VLO
#define AKV1   (6*TILE_B)           // buffer 1
#define AEXM   (10*TILE_B)          // max exchange: 8 warps * 64 floats
#define AEXS   (AEXM + 2048)        // sum exchange
#define ASM_TOT (AEXS + 2048)       // 96256

__device__ __forceinline__ void stage_kv(uint32_t sdst, int b, int kt, int tid) {
    const __nv_bfloat16* Kh = g_Khi + ((size_t)b * T_ + kt*64) * H_;
    const __nv_bfloat16* Kl = g_Klo + ((size_t)b * T_ + kt*64) * H_;
    #pragma unroll
    for (int it = tid; it < 512; it += 256) {
        int r = it >> 3, s = it & 7;
        uint32_t off = (uint32_t)(r * (ASTR*2) + s*16);
        CP_A16(sdst + off,            Kh + r*64 + s*8);
        CP_A16(sdst + TILE_B + off,   Kl + r*64 + s*8);
        size_t vsrc = ((size_t)b * H_ + r) * T_ + kt*64 + s*8;
        CP_A16(sdst + 2*TILE_B + off, g_VThi + vsrc);
        CP_A16(sdst + 3*TILE_B + off, g_VTlo + vsrc);
    }
}

__global__ __launch_bounds__(256) void attn_mma_kernel(float* __restrict__ out)
{
    extern __shared__ char smem[];
    const uint32_t sbase = smem_u32(smem);
    const int tid  = threadIdx.x;
    const int wid  = tid >> 5;
    const int lane = tid & 31;
    const int rw   = wid & 3;       // row group: q rows rw*16..+15
    const int ch   = wid >> 2;      // kv-column half: cols ch*32..+31
    const int b    = blockIdx.y;
    const int r8   = lane & 7;
    const int mlo  = (lane >> 3) & 1;
    const int khi  = (lane >> 4) & 1;
    const int g    = lane >> 2;
    const int tq   = lane & 3;
    const float scale = 0.125f;

    float* exm = reinterpret_cast<float*>(smem + AEXM);
    float* exs = reinterpret_cast<float*>(smem + AEXS);

    const uint32_t aRowOff = (uint32_t)((rw*16 + mlo*8 + r8) * (ASTR*2) + khi*16);
    uint32_t bOffS[2];
    #pragma unroll
    for (int pp = 0; pp < 2; pp++) {
        int p = 2*ch + pp;
        bOffS[pp] = (uint32_t)((p*16 + khi*8 + r8) * (ASTR*2) + mlo*16);
    }
    uint32_t bOffV[4];
    #pragma unroll
    for (int p = 0; p < 4; p++)
        bOffV[p] = (uint32_t)((p*16 + khi*8 + r8) * (ASTR*2) + mlo*16);

    #pragma unroll 1
    for (int pass = 0; pass < 2; pass++) {
        const int qt = pass ? (31 - (int)blockIdx.x) : (int)blockIdx.x;

        __syncthreads();   // all buffers free from previous pass

        {
            const __nv_bfloat16* Qh = g_Qhi + ((size_t)b * T_ + qt*64) * H_;
            const __nv_bfloat16* Ql = g_Qlo + ((size_t)b * T_ + qt*64) * H_;
            #pragma unroll
            for (int it = tid; it < 512; it += 256) {
                int r = it >> 3, s = it & 7;
                uint32_t off = (uint32_t)(r * (ASTR*2) + s*16);
                CP_A16(sbase + AQHI + off, Qh + r*64 + s*8);
                CP_A16(sbase + AQLO + off, Ql + r*64 + s*8);
            }
            stage_kv(sbase + AKV0, b, 0, tid);
            CP_COMMIT();
        }
        CP_WAIT0();
        __syncthreads();

        uint32_t qh[4][4], ql[4][4];
        #pragma unroll
        for (int ks = 0; ks < 4; ks++) {
            ldmx4(qh[ks][0], qh[ks][1], qh[ks][2], qh[ks][3], sbase + AQHI + aRowOff + ks*32);
            ldmx4(ql[ks][0], ql[ks][1], ql[ks][2], ql[ks][3], sbase + AQLO + aRowOff + ks*32);
        }

        float m0r = -1e30f, m1r = -1e30f, l0 = 0.f, l1 = 0.f;
        float o[8][4];
        #pragma unroll
        for (int nt = 0; nt < 8; nt++)
            #pragma unroll
            for (int q = 0; q < 4; q++) o[nt][q] = 0.f;

        #pragma unroll 1
        for (int kt = 0; kt <= qt; kt++) {
            const uint32_t kvb = sbase + ((kt & 1) ? AKV1 : AKV0);

            if (kt < qt) {
                stage_kv(sbase + (((kt + 1) & 1) ? AKV1 : AKV0), b, kt + 1, tid);
                CP_COMMIT();
                CP_WAIT1();
            } else {
                CP_WAIT0();
            }
            __syncthreads();

            // ---- S = Q K^T for this warp's 32 kv cols (3 split passes) ----
            float s_[4][4];
            #pragma unroll
            for (int nt = 0; nt < 4; nt++)
                #pragma unroll
                for (int q = 0; q < 4; q++) s_[nt][q] = 0.f;

            #pragma unroll
            for (int ks = 0; ks < 4; ks++) {
                uint32_t kb = (uint32_t)(ks * 32);
                uint32_t kh_[2][4], kl_[2][4];
                #pragma unroll
                for (int pp = 0; pp < 2; pp++) {
                    ldmx4(kh_[pp][0], kh_[pp][1], kh_[pp][2], kh_[pp][3], kvb + bOffS[pp] + kb);
                    ldmx4(kl_[pp][0], kl_[pp][1], kl_[pp][2], kl_[pp][3], kvb + TILE_B + bOffS[pp] + kb);
                }
                #pragma unroll
                for (int pp = 0; pp < 2; pp++) {
                    mma16816(s_[2*pp],   qh[ks][0], qh[ks][1], qh[ks][2], qh[ks][3], kh_[pp][0], kh_[pp][1]);
                    mma16816(s_[2*pp+1], qh[ks][0], qh[ks][1], qh[ks][2], qh[ks][3], kh_[pp][2], kh_[pp][3]);
                    mma16816(s_[2*pp],   qh[ks][0], qh[ks][1], qh[ks][2], qh[ks][3], kl_[pp][0], kl_[pp][1]);
                    mma16816(s_[2*pp+1], qh[ks][0], qh[ks][1], qh[ks][2], qh[ks][3], kl_[pp][2], kl_[pp][3]);
                    mma16816(s_[2*pp],   ql[ks][0], ql[ks][1], ql[ks][2], ql[ks][3], kh_[pp][0], kh_[pp][1]);
                    mma16816(s_[2*pp+1], ql[ks][0], ql[ks][1], ql[ks][2], ql[ks][3], kh_[pp][2], kh_[pp][3]);
                }
            }

            #pragma unroll
            for (int nt = 0; nt < 4; nt++)
                #pragma unroll
                for (int q = 0; q < 4; q++) s_[nt][q] *= scale;
            if (kt == qt) {
                int qr0 = qt*64 + rw*16 + g;
                #pragma unroll
                for (int nt = 0; nt < 4; nt++) {
                    int kc0 = kt*64 + ch*32 + nt*8 + 2*tq;
                    if (kc0     > qr0)     s_[nt][0] = -1e30f;
                    if (kc0 + 1 > qr0)     s_[nt][1] = -1e30f;
                    if (kc0     > qr0 + 8) s_[nt][2] = -1e30f;
                    if (kc0 + 1 > qr0 + 8) s_[nt][3] = -1e30f;
                }
            }

            // ---- online softmax, cross-warp max/sum merge ----
            float mx0 = -1e30f, mx1 = -1e30f;
            #pragma unroll
            for (int nt = 0; nt < 4; nt++) {
                mx0 = fmaxf(mx0, fmaxf(s_[nt][0], s_[nt][1]));
                mx1 = fmaxf(mx1, fmaxf(s_[nt][2], s_[nt][3]));
            }
            mx0 = fmaxf(mx0, __shfl_xor_sync(0xffffffffu, mx0, 1));
            mx0 = fmaxf(mx0, __shfl_xor_sync(0xffffffffu, mx0, 2));
            mx1 = fmaxf(mx1, __shfl_xor_sync(0xffffffffu, mx1, 1));
            mx1 = fmaxf(mx1, __shfl_xor_sync(0xffffffffu, mx1, 2));
            exm[wid*64 + lane]      = mx0;
            exm[wid*64 + 32 + lane] = mx1;
            __syncthreads();
            mx0 = fmaxf(mx0, exm[(wid^4)*64 + lane]);
            mx1 = fmaxf(mx1, exm[(wid^4)*64 + 32 + lane]);

            float mn0 = fmaxf(m0r, mx0), mn1 = fmaxf(m1r, mx1);
            float al0 = __expf(m0r - mn0), al1 = __expf(m1r - mn1);
            float rs0 = 0.f, rs1 = 0.f;
            #pragma unroll
            for (int nt = 0; nt < 4; nt++) {
                s_[nt][0] = __expf(s_[nt][0] - mn0);
                s_[nt][1] = __expf(s_[nt][1] - mn0);
                s_[nt][2] = __expf(s_[nt][2] - mn1);
                s_[nt][3] = __expf(s_[nt][3] - mn1);
                rs0 += s_[nt][0] + s_[nt][1];
                rs1 += s_[nt][2] + s_[nt][3];
            }
            rs0 += __shfl_xor_sync(0xffffffffu, rs0, 1);
            rs0 += __shfl_xor_sync(0xffffffffu, rs0, 2);
            rs1 += __shfl_xor_sync(0xffffffffu, rs1, 1);
            rs1 += __shfl_xor_sync(0xffffffffu, rs1, 2);
            exs[wid*64 + lane]      = rs0;
            exs[wid*64 + 32 + lane] = rs1;
            __syncthreads();
            rs0 += exs[(wid^4)*64 + lane];
            rs1 += exs[(wid^4)*64 + 32 + lane];

            l0 = l0 * al0 + rs0;  l1 = l1 * al1 + rs1;
            m0r = mn0;  m1r = mn1;
            #pragma unroll
            for (int nt = 0; nt < 8; nt++) {
                o[nt][0] *= al0; o[nt][1] *= al0;
                o[nt][2] *= al1; o[nt][3] *= al1;
            }

            // ---- O_partial += P V over this warp's 32 kv positions ----
            #pragma unroll
            for (int kkl = 0; kkl < 2; kkl++) {
                uint32_t ah[4], al_[4];
                ah[0] = bf16x2(s_[2*kkl][0],   s_[2*kkl][1]);
                ah[1] = bf16x2(s_[2*kkl][2],   s_[2*kkl][3]);
                ah[2] = bf16x2(s_[2*kkl+1][0], s_[2*kkl+1][1]);
                ah[3] = bf16x2(s_[2*kkl+1][2], s_[2*kkl+1][3]);
                al_[0] = bf16x2(bf16lo_res(s_[2*kkl][0]),   bf16lo_res(s_[2*kkl][1]));
                al_[1] = bf16x2(bf16lo_res(s_[2*kkl][2]),   bf16lo_res(s_[2*kkl][3]));
                al_[2] = bf16x2(bf16lo_res(s_[2*kkl+1][0]), bf16lo_res(s_[2*kkl+1][1]));
                al_[3] = bf16x2(bf16lo_res(s_[2*kkl+1][2]), bf16lo_res(s_[2*kkl+1][3]));
                uint32_t kb = (uint32_t)((ch*2 + kkl) * 32);
                #pragma unroll
                for (int p = 0; p < 4; p++) {
                    uint32_t vh0, vh1, vh2, vh3, vl0, vl1, vl2, vl3;
                    ldmx4(vh0, vh1, vh2, vh3, kvb + 2*TILE_B + bOffV[p] + kb);
                    ldmx4(vl0, vl1, vl2, vl3, kvb + 3*TILE_B + bOffV[p] + kb);
                    mma16816(o[2*p],   ah[0], ah[1], ah[2], ah[3], vh0, vh1);
                    mma16816(o[2*p+1], ah[0], ah[1], ah[2], ah[3], vh2, vh3);
                    mma16816(o[2*p],   ah[0], ah[1], ah[2], ah[3], vl0, vl1);
                    mma16816(o[2*p+1], ah[0], ah[1], ah[2], ah[3], vl2, vl3);
                    mma16816(o[2*p],   al_[0], al_[1], al_[2], al_[3], vh0, vh1);
                    mma16816(o[2*p+1], al_[0], al_[1], al_[2], al_[3], vh2, vh3);
                }
            }
            __syncthreads();   // all warps done reading kt's buffer
        }

        // ---- merge partner-warp O partials (kv-reduction halves) ----
        float* om = reinterpret_cast<float*>(smem + AKV0);  // [64][66]
        if (ch == 1) {
            #pragma unroll
            for (int nt = 0; nt < 8; nt++) {
                int col = nt*8 + 2*tq;
                om[(rw*16 + g)*66 + col]       = o[nt][0];
                om[(rw*16 + g)*66 + col + 1]   = o[nt][1];
                om[(rw*16 + g + 8)*66 + col]     = o[nt][2];
                om[(rw*16 + g + 8)*66 + col + 1] = o[nt][3];
            }
        }
        __syncthreads();
        if (ch == 0) {
            float rc0 = 1.f / l0, rc1 = 1.f / l1;
            int qr0 = qt*64 + rw*16 + g;
            #pragma unroll
            for (int nt = 0; nt < 8; nt++) {
                int col = nt*8 + 2*tq;
                float v0 = (o[nt][0] + om[(rw*16 + g)*66 + col])       * rc0;
                float v1 = (o[nt][1] + om[(rw*16 + g)*66 + col + 1])   * rc0;
                float v2 = (o[nt][2] + om[(rw*16 + g + 8)*66 + col])     * rc1;
                float v3 = (o[nt][3] + om[(rw*16 + g + 8)*66 + col + 1]) * rc1;
                *reinterpret_cast<float2*>(&out[((size_t)b*T_ + qr0) * H_ + col]) =
                    make_float2(v0, v1);
                *reinterpret_cast<float2*>(&out[((size_t)b*T_ + qr0 + 8) * H_ + col]) =
                    make_float2(v2, v3);
            }
        }
    }
}

extern "C" void kernel_launch(void* const* d_in, const int* in_sizes, int n_in,
                              void* d_out, int out_size)
{
    const float* x  = (const float*)d_in[0];
    const float* Wq = (const float*)d_in[1];
    const float* Wk = (const float*)d_in[2];
    const float* Wv = (const float*)d_in[3];
    float* out = (float*)d_out;

    cudaFuncSetAttribute(proj_gemm_kernel,
                         cudaFuncAttributeMaxDynamicSharedMemorySize, SM_TOT);
    cudaFuncSetAttribute(attn_mma_kernel,
                         cudaFuncAttributeMaxDynamicSharedMemorySize, ASM_TOT);

    prep_B_kernel<<<(192 * 1024) / 256, 256>>>(Wq, Wk, Wv);
    proj_gemm_kernel<<<(B_ * T_) / 128, 512, SM_TOT>>>(x);
    attn_mma_kernel<<<dim3(16, B_), 256, ASM_TOT>>>(out);
}

// round 8
// speedup vs baseline: 1.0173x; 1.0173x over previous
#include <cuda_runtime.h>
#include <cuda_bf16.h>
#include <math.h>
#include <stdint.h>

#define B_ 8
#define T_ 2048
#define C_ 1024
#define H_ 64
#define CHUNK 8          // KV tiles per attention CTA

// Q/K post-RoPE, bf16 hi/lo, row-major [B*T][64]
__device__ __align__(16) __nv_bfloat16 g_Qhi[B_*T_*H_];
__device__ __align__(16) __nv_bfloat16 g_Qlo[B_*T_*H_];
__device__ __align__(16) __nv_bfloat16 g_Khi[B_*T_*H_];
__device__ __align__(16) __nv_bfloat16 g_Klo[B_*T_*H_];
// V transposed [B][64 h][T], bf16 hi/lo
__device__ __align__(16) __nv_bfloat16 g_VThi[B_*H_*T_];
__device__ __align__(16) __nv_bfloat16 g_VTlo[B_*H_*T_];
// W split bf16 hi/lo, K-major [192][1024]
__device__ __align__(16) __nv_bfloat16 g_Bhi[192*1024];
__device__ __align__(16) __nv_bfloat16 g_Blo[192*1024];
// split-KV partials: part index p = (b*32 + qt)*4 + chunk
__device__ __align__(16) float g_Opart[B_*32*4*64*64];   // 16.8 MB
__device__ float g_mpart[B_*32*4*64];
__device__ float g_lpart[B_*32*4*64];

__device__ __forceinline__ uint32_t smem_u32(const void* p) {
    uint32_t a;
    asm("{ .reg .u64 t; cvta.to.shared.u64 t, %1; cvt.u32.u64 %0, t; }" : "=r"(a) : "l"(p));
    return a;
}
__device__ __forceinline__ void ldmx4(uint32_t& r0, uint32_t& r1, uint32_t& r2, uint32_t& r3,
                                      uint32_t addr) {
    asm volatile("ldmatrix.sync.aligned.m8n8.x4.shared.b16 {%0,%1,%2,%3}, [%4];"
                 : "=r"(r0), "=r"(r1), "=r"(r2), "=r"(r3) : "r"(addr));
}
__device__ __forceinline__ void mma16816(float* c,
                                         uint32_t a0, uint32_t a1, uint32_t a2, uint32_t a3,
                                         uint32_t b0, uint32_t b1) {
    asm volatile("mma.sync.aligned.m16n8k16.row.col.f32.bf16.bf16.f32 "
                 "{%0,%1,%2,%3}, {%4,%5,%6,%7}, {%8,%9}, {%0,%1,%2,%3};"
                 : "+f"(c[0]), "+f"(c[1]), "+f"(c[2]), "+f"(c[3])
                 : "r"(a0), "r"(a1), "r"(a2), "r"(a3), "r"(b0), "r"(b1));
}
__device__ __forceinline__ uint32_t bf16x2(float a, float b) {
    __nv_bfloat16 h0 = __float2bfloat16(a), h1 = __float2bfloat16(b);
    return (uint32_t)__bfloat16_as_ushort(h0) | ((uint32_t)__bfloat16_as_ushort(h1) << 16);
}
__device__ __forceinline__ float bf16lo_res(float v) {
    return v - __bfloat162float(__float2bfloat16(v));
}
#define CP_A16(dst, src) \
    asm volatile("cp.async.cg.shared.global [%0], [%1], 16;" :: "r"(dst), "l"(src))
#define CP_COMMIT() asm volatile("cp.async.commit_group;" ::: "memory")
#define CP_WAIT0()  asm volatile("cp.async.wait_group 0;" ::: "memory")

// ---------------------------------------------------------------------------
// Prep: split W{q,k,v} into bf16 hi/lo, K-major [192][1024]
// ---------------------------------------------------------------------------
__global__ __launch_bounds__(256) void prep_B_kernel(
    const float* __restrict__ Wq, const float* __restrict__ Wk, const float* __restrict__ Wv)
{
    int idx = blockIdx.x * 256 + threadIdx.x;
    int n = idx >> 10, k = idx & 1023;
    const float* W = (n < 64) ? Wq : (n < 128) ? Wk : Wv;
    float v = W[k * 64 + (n & 63)];
    __nv_bfloat16 h = __float2bfloat16(v);
    g_Bhi[idx] = h;
    g_Blo[idx] = __float2bfloat16(v - __bfloat162float(h));
}

// ---------------------------------------------------------------------------
// Projection GEMM (HMMA bf16 hi/lo split). M=128 x N=192 per CTA, 16 warps.
// Epilogue: RoPE, write Q/K bf16 hi/lo row-major; V bf16 hi/lo transposed.
// ---------------------------------------------------------------------------
#define PA_STR 72
#define SM_AHI 0
#define SM_ALO (128*PA_STR*2)
#define SM_BHI (2*128*PA_STR*2)
#define SM_BLO (SM_BHI + 192*PA_STR*2)
#define SM_TOT (SM_BLO + 192*PA_STR*2)

__global__ __launch_bounds__(512) void proj_gemm_kernel(const float* __restrict__ x)
{
    extern __shared__ char smem[];
    const uint32_t sbase = smem_u32(smem);
    const int tid    = threadIdx.x;
    const int wid    = tid >> 5;
    const int lane   = tid & 31;
    const int warp_m = wid >> 2;
    const int warp_n = wid & 3;
    const int m0     = blockIdx.x * 128;

    uint32_t aOff[2], bOff[3];
    {
        int mlo = (lane >> 3) & 1, khi = (lane >> 4) & 1, r8 = lane & 7;
        #pragma unroll
        for (int mt = 0; mt < 2; mt++)
            aOff[mt] = (uint32_t)((warp_m*32 + mt*16 + mlo*8 + r8) * (PA_STR*2) + khi*16);
        #pragma unroll
        for (int p = 0; p < 3; p++)
            bOff[p] = (uint32_t)((warp_n*48 + p*16 + khi*8 + r8) * (PA_STR*2) + mlo*16);
    }

    float acc[2][6][4];
    #pragma unroll
    for (int mt = 0; mt < 2; mt++)
        #pragma unroll
        for (int nt = 0; nt < 6; nt++)
            #pragma unroll
            for (int q = 0; q < 4; q++) acc[mt][nt][q] = 0.f;

    #pragma unroll 1
    for (int c = 0; c < 16; c++) {
        const int kc = c * 64;
        if (c > 0) __syncthreads();

        #pragma unroll
        for (int it = tid; it < 2048; it += 512) {
            int r = it >> 4, q = it & 15;
            float4 f = *reinterpret_cast<const float4*>(x + (size_t)(m0 + r) * C_ + kc + q*4);
            uint32_t h0 = bf16x2(f.x, f.y), h1 = bf16x2(f.z, f.w);
            uint32_t l0 = bf16x2(bf16lo_res(f.x), bf16lo_res(f.y));
            uint32_t l1 = bf16x2(bf16lo_res(f.z), bf16lo_res(f.w));
            uint32_t off = (uint32_t)(r * (PA_STR*2) + q * 8);
            *reinterpret_cast<uint2*>(smem + SM_AHI + off) = make_uint2(h0, h1);
            *reinterpret_cast<uint2*>(smem + SM_ALO + off) = make_uint2(l0, l1);
        }
        #pragma unroll
        for (int it = tid; it < 1536; it += 512) {
            int n = it >> 3, s = it & 7;
            uint32_t off = (uint32_t)(n * (PA_STR*2) + s * 16);
            *reinterpret_cast<uint4*>(smem + SM_BHI + off) =
                *reinterpret_cast<const uint4*>(g_Bhi + (size_t)n * 1024 + kc + s*8);
            *reinterpret_cast<uint4*>(smem + SM_BLO + off) =
                *reinterpret_cast<const uint4*>(g_Blo + (size_t)n * 1024 + kc + s*8);
        }
        __syncthreads();

        #pragma unroll 1
        for (int pass = 0; pass < 3; pass++) {
            uint32_t aBase = sbase + ((pass < 2) ? SM_AHI : SM_ALO);
            uint32_t bBase = sbase + ((pass == 1) ? SM_BLO : SM_BHI);
            #pragma unroll
            for (int ks = 0; ks < 4; ks++) {
                uint32_t kb = (uint32_t)(ks * 32);
                uint32_t a[2][4];
                #pragma unroll
                for (int mt = 0; mt < 2; mt++)
                    ldmx4(a[mt][0], a[mt][1], a[mt][2], a[mt][3], aBase + aOff[mt] + kb);
                uint32_t b[6][2];
                #pragma unroll
                for (int p = 0; p < 3; p++) {
                    uint32_t r0, r1, r2, r3;
                    ldmx4(r0, r1, r2, r3, bBase + bOff[p] + kb);
                    b[p*2][0] = r0; b[p*2][1] = r1;
                    b[p*2+1][0] = r2; b[p*2+1][1] = r3;
                }
                #pragma unroll
                for (int mt = 0; mt < 2; mt++)
                    #pragma unroll
                    for (int nt = 0; nt < 6; nt++)
                        mma16816(acc[mt][nt], a[mt][0], a[mt][1], a[mt][2], a[mt][3],
                                 b[nt][0], b[nt][1]);
            }
        }
    }

    const int g  = lane >> 2;
    const int tq = lane & 3;
    #pragma unroll
    for (int mt = 0; mt < 2; mt++) {
        int row0 = m0 + warp_m*32 + mt*16 + g;
        int rows[2] = { row0, row0 + 8 };
        #pragma unroll
        for (int nt = 0; nt < 6; nt++) {
            int col = warp_n*48 + nt*8 + 2*tq;
            int mat = col >> 6;
            int col_in = col & 63;
            if (mat < 2) {
                __nv_bfloat16* dhi = (mat == 0) ? g_Qhi : g_Khi;
                __nv_bfloat16* dlo = (mat == 0) ? g_Qlo : g_Klo;
                int pi = col_in >> 1;
                float inv = powf(10000.f, -(float)pi * (1.f / 32.f));
                #pragma unroll
                for (int rg = 0; rg < 2; rg++) {
                    int t = rows[rg] & (T_ - 1);
                    float sn, cs;
                    sincosf((float)t * inv, &sn, &cs);
                    float a0 = acc[mt][nt][rg*2], a1 = acc[mt][nt][rg*2 + 1];
                    float v0 = a0*cs - a1*sn, v1 = a1*cs + a0*sn;
                    size_t base = (size_t)rows[rg] * H_ + col_in;
                    *reinterpret_cast<uint32_t*>(&dhi[base]) = bf16x2(v0, v1);
                    *reinterpret_cast<uint32_t*>(&dlo[base]) = bf16x2(bf16lo_res(v0), bf16lo_res(v1));
                }
            } else {
                #pragma unroll
                for (int rg = 0; rg < 2; rg++) {
                    int bb = rows[rg] >> 11, tt = rows[rg] & (T_ - 1);
                    #pragma unroll
                    for (int e = 0; e < 2; e++) {
                        float v = acc[mt][nt][rg*2 + e];
                        size_t idx = ((size_t)bb * H_ + (col_in + e)) * T_ + tt;
                        g_VThi[idx] = __float2bfloat16(v);
                        g_VTlo[idx] = __float2bfloat16(bf16lo_res(v));
                    }
                }
            }
        }
    }
}

// ---------------------------------------------------------------------------
// Split-KV attention partial: one CTA = (b, qt, chunk of <=8 KV tiles).
// 4 warps x 16 q rows (R6 structure). Emits un-normalized O, m, l.
// Single KV buffer (6 smem tiles = 54KB) -> 3 CTAs/SM co-resident.
// ---------------------------------------------------------------------------
#define ASTR   72
#define TILE_B (64*ASTR*2)          // 9216 bytes per 64x64 bf16 tile
#define AQHI   0
#define AQLO   TILE_B
#define AKV    (2*TILE_B)           // KHI,KLO,VHI,VLO
#define ASM_TOT (6*TILE_B)          // 55296

__device__ __forceinline__ void stage_kv(uint32_t sdst, int b, int kt, int tid) {
    const __nv_bfloat16* Kh = g_Khi + ((size_t)b * T_ + kt*64) * H_;
    const __nv_bfloat16* Kl = g_Klo + ((size_t)b * T_ + kt*64) * H_;
    #pragma unroll
    for (int it = tid; it < 512; it += 128) {
        int r = it >> 3, s = it & 7;
        uint32_t off = (uint32_t)(r * (ASTR*2) + s*16);
        CP_A16(sdst + off,            Kh + r*64 + s*8);
        CP_A16(sdst + TILE_B + off,   Kl + r*64 + s*8);
        size_t vsrc = ((size_t)b * H_ + r) * T_ + kt*64 + s*8;
        CP_A16(sdst + 2*TILE_B + off, g_VThi + vsrc);
        CP_A16(sdst + 3*TILE_B + off, g_VTlo + vsrc);
    }
}

__global__ __launch_bounds__(128, 3) void attn_part_kernel()
{
    extern __shared__ char smem[];
    const uint32_t sbase = smem_u32(smem);
    const int tid  = threadIdx.x;
    const int wid  = tid >> 5;
    const int lane = tid & 31;
    const int b    = blockIdx.y;
    const int r8   = lane & 7;
    const int mlo  = (lane >> 3) & 1;
    const int khi  = (lane >> 4) & 1;
    const int g    = lane >> 2;
    const int tq   = lane & 3;
    const float scale = 0.125f;

    // map blockIdx.x (0..79) -> (qt, chunk); qt has (qt>>3)+1 chunks
    int qt = 0, chunk = 0;
    {
        int bx = blockIdx.x, acc = 0;
        #pragma unroll 1
        for (int q = 0; q < 32; q++) {
            int nc = (q >> 3) + 1;
            if (bx < acc + nc) { qt = q; chunk = bx - acc; break; }
            acc += nc;
        }
    }
    const int kt0 = chunk * CHUNK;
    const int kt1 = (kt0 + CHUNK - 1 < qt) ? (kt0 + CHUNK - 1) : qt;
    const int part = (b*32 + qt)*4 + chunk;

    const uint32_t aRowOff = (uint32_t)((wid*16 + mlo*8 + r8) * (ASTR*2) + khi*16);
    uint32_t bRowOff[4];
    #pragma unroll
    for (int p = 0; p < 4; p++)
        bRowOff[p] = (uint32_t)((p*16 + khi*8 + r8) * (ASTR*2) + mlo*16);

    // ---- stage Q + first KV tile ----
    {
        const __nv_bfloat16* Qh = g_Qhi + ((size_t)b * T_ + qt*64) * H_;
        const __nv_bfloat16* Ql = g_Qlo + ((size_t)b * T_ + qt*64) * H_;
        #pragma unroll
        for (int it = tid; it < 512; it += 128) {
            int r = it >> 3, s = it & 7;
            uint32_t off = (uint32_t)(r * (ASTR*2) + s*16);
            CP_A16(sbase + AQHI + off, Qh + r*64 + s*8);
            CP_A16(sbase + AQLO + off, Ql + r*64 + s*8);
        }
        stage_kv(sbase + AKV, b, kt0, tid);
        CP_COMMIT();
    }
    CP_WAIT0();
    __syncthreads();

    uint32_t qh[4][4], ql[4][4];
    #pragma unroll
    for (int ks = 0; ks < 4; ks++) {
        ldmx4(qh[ks][0], qh[ks][1], qh[ks][2], qh[ks][3], sbase + AQHI + aRowOff + ks*32);
        ldmx4(ql[ks][0], ql[ks][1], ql[ks][2], ql[ks][3], sbase + AQLO + aRowOff + ks*32);
    }

    float m0r = -1e30f, m1r = -1e30f, l0 = 0.f, l1 = 0.f;
    float o[8][4];
    #pragma unroll
    for (int nt = 0; nt < 8; nt++)
        #pragma unroll
        for (int q = 0; q < 4; q++) o[nt][q] = 0.f;

    #pragma unroll 1
    for (int kt = kt0; kt <= kt1; kt++) {
        const uint32_t kvb = sbase + AKV;

        // ---- S = Q K^T (3 split passes, fp32 accum) ----
        float s_[8][4];
        #pragma unroll
        for (int nt = 0; nt < 8; nt++)
            #pragma unroll
            for (int q = 0; q < 4; q++) s_[nt][q] = 0.f;

        #pragma unroll
        for (int ks = 0; ks < 4; ks++) {
            uint32_t kb = (uint32_t)(ks * 32);
            uint32_t kh_[4][4], kl_[4][4];
            #pragma unroll
            for (int p = 0; p < 4; p++) {
                ldmx4(kh_[p][0], kh_[p][1], kh_[p][2], kh_[p][3], kvb + bRowOff[p] + kb);
                ldmx4(kl_[p][0], kl_[p][1], kl_[p][2], kl_[p][3], kvb + TILE_B + bRowOff[p] + kb);
            }
            #pragma unroll
            for (int p = 0; p < 4; p++) {
                mma16816(s_[2*p],   qh[ks][0], qh[ks][1], qh[ks][2], qh[ks][3], kh_[p][0], kh_[p][1]);
                mma16816(s_[2*p+1], qh[ks][0], qh[ks][1], qh[ks][2], qh[ks][3], kh_[p][2], kh_[p][3]);
                mma16816(s_[2*p],   qh[ks][0], qh[ks][1], qh[ks][2], qh[ks][3], kl_[p][0], kl_[p][1]);
                mma16816(s_[2*p+1], qh[ks][0], qh[ks][1], qh[ks][2], qh[ks][3], kl_[p][2], kl_[p][3]);
                mma16816(s_[2*p],   ql[ks][0], ql[ks][1], ql[ks][2], ql[ks][3], kh_[p][0], kh_[p][1]);
                mma16816(s_[2*p+1], ql[ks][0], ql[ks][1], ql[ks][2], ql[ks][3], kh_[p][2], kh_[p][3]);
            }
        }

        #pragma unroll
        for (int nt = 0; nt < 8; nt++)
            #pragma unroll
            for (int q = 0; q < 4; q++) s_[nt][q] *= scale;
        if (kt == qt) {
            int qr0 = qt*64 + wid*16 + g;
            #pragma unroll
            for (int nt = 0; nt < 8; nt++) {
                int kc0 = kt*64 + nt*8 + 2*tq;
                if (kc0     > qr0)     s_[nt][0] = -1e30f;
                if (kc0 + 1 > qr0)     s_[nt][1] = -1e30f;
                if (kc0     > qr0 + 8) s_[nt][2] = -1e30f;
                if (kc0 + 1 > qr0 + 8) s_[nt][3] = -1e30f;
            }
        }

        // ---- online softmax ----
        float mx0 = -1e30f, mx1 = -1e30f;
        #pragma unroll
        for (int nt = 0; nt < 8; nt++) {
            mx0 = fmaxf(mx0, fmaxf(s_[nt][0], s_[nt][1]));
            mx1 = fmaxf(mx1, fmaxf(s_[nt][2], s_[nt][3]));
        }
        mx0 = fmaxf(mx0, __shfl_xor_sync(0xffffffffu, mx0, 1));
        mx0 = fmaxf(mx0, __shfl_xor_sync(0xffffffffu, mx0, 2));
        mx1 = fmaxf(mx1, __shfl_xor_sync(0xffffffffu, mx1, 1));
        mx1 = fmaxf(mx1, __shfl_xor_sync(0xffffffffu, mx1, 2));
        float mn0 = fmaxf(m0r, mx0), mn1 = fmaxf(m1r, mx1);
        float al0 = __expf(m0r - mn0), al1 = __expf(m1r - mn1);
        float rs0 = 0.f, rs1 = 0.f;
        #pragma unroll
        for (int nt = 0; nt < 8; nt++) {
            s_[nt][0] = __expf(s_[nt][0] - mn0);
            s_[nt][1] = __expf(s_[nt][1] - mn0);
            s_[nt][2] = __expf(s_[nt][2] - mn1);
            s_[nt][3] = __expf(s_[nt][3] - mn1);
            rs0 += s_[nt][0] + s_[nt][1];
            rs1 += s_[nt][2] + s_[nt][3];
        }
        rs0 += __shfl_xor_sync(0xffffffffu, rs0, 1);
        rs0 += __shfl_xor_sync(0xffffffffu, rs0, 2);
        rs1 += __shfl_xor_sync(0xffffffffu, rs1, 1);
        rs1 += __shfl_xor_sync(0xffffffffu, rs1, 2);
        l0 = l0 * al0 + rs0;  l1 = l1 * al1 + rs1;
        m0r = mn0;  m1r = mn1;
        #pragma unroll
        for (int nt = 0; nt < 8; nt++) {
            o[nt][0] *= al0; o[nt][1] *= al0;
            o[nt][2] *= al1; o[nt][3] *= al1;
        }

        // ---- O += P V ----
        #pragma unroll
        for (int kk = 0; kk < 4; kk++) {
            uint32_t ah[4], al_[4];
            ah[0] = bf16x2(s_[2*kk][0],   s_[2*kk][1]);
            ah[1] = bf16x2(s_[2*kk][2],   s_[2*kk][3]);
            ah[2] = bf16x2(s_[2*kk+1][0], s_[2*kk+1][1]);
            ah[3] = bf16x2(s_[2*kk+1][2], s_[2*kk+1][3]);
            al_[0] = bf16x2(bf16lo_res(s_[2*kk][0]),   bf16lo_res(s_[2*kk][1]));
            al_[1] = bf16x2(bf16lo_res(s_[2*kk][2]),   bf16lo_res(s_[2*kk][3]));
            al_[2] = bf16x2(bf16lo_res(s_[2*kk+1][0]), bf16lo_res(s_[2*kk+1][1]));
            al_[3] = bf16x2(bf16lo_res(s_[2*kk+1][2]), bf16lo_res(s_[2*kk+1][3]));
            uint32_t kb = (uint32_t)(kk * 32);
            #pragma unroll
            for (int p = 0; p < 4; p++) {
                uint32_t vh0, vh1, vh2, vh3, vl0, vl1, vl2, vl3;
                ldmx4(vh0, vh1, vh2, vh3, kvb + 2*TILE_B + bRowOff[p] + kb);
                ldmx4(vl0, vl1, vl2, vl3, kvb + 3*TILE_B + bRowOff[p] + kb);
                mma16816(o[2*p],   ah[0], ah[1], ah[2], ah[3], vh0, vh1);
                mma16816(o[2*p+1], ah[0], ah[1], ah[2], ah[3], vh2, vh3);
                mma16816(o[2*p],   ah[0], ah[1], ah[2], ah[3], vl0, vl1);
                mma16816(o[2*p+1], ah[0], ah[1], ah[2], ah[3], vl2, vl3);
                mma16816(o[2*p],   al_[0], al_[1], al_[2], al_[3], vh0, vh1);
                mma16816(o[2*p+1], al_[0], al_[1], al_[2], al_[3], vh2, vh3);
            }
        }

        // rotate single buffer: stage next tile after everyone finished reading
        __syncthreads();
        if (kt < kt1) {
            stage_kv(sbase + AKV, b, kt + 1, tid);
            CP_COMMIT();
            CP_WAIT0();
            __syncthreads();
        }
    }

    // ---- write partials (un-normalized) ----
    {
        int row0 = wid*16 + g;
        float* Op = g_Opart + (size_t)part * 64 * 64;
        #pragma unroll
        for (int nt = 0; nt < 8; nt++) {
            int col = nt*8 + 2*tq;
            *reinterpret_cast<float2*>(&Op[(row0)     * 64 + col]) = make_float2(o[nt][0], o[nt][1]);
            *reinterpret_cast<float2*>(&Op[(row0 + 8) * 64 + col]) = make_float2(o[nt][2], o[nt][3]);
        }
        if (tq == 0) {
            g_mpart[part*64 + row0]     = m0r;
            g_mpart[part*64 + row0 + 8] = m1r;
            g_lpart[part*64 + row0]     = l0;
            g_lpart[part*64 + row0 + 8] = l1;
        }
    }
}

// ---------------------------------------------------------------------------
// Merge: combine <=4 chunk partials per (b, qt), normalize, write output.
// grid (32, 8) x 256 threads; 4 threads per row, 16 cols each.
// ---------------------------------------------------------------------------
__global__ __launch_bounds__(256) void attn_merge_kernel(float* __restrict__ out)
{
    const int qt = blockIdx.x, b = blockIdx.y;
    const int nc = (qt >> 3) + 1;
    const int r  = threadIdx.x >> 2;
    const int cb = (threadIdx.x & 3) * 16;
    const int pbase = (b*32 + qt)*4;

    float m = -1e30f;
    #pragma unroll
    for (int c = 0; c < 4; c++)
        if (c < nc) m = fmaxf(m, g_mpart[(pbase + c)*64 + r]);
    float w[4];
    float l = 0.f;
    #pragma unroll
    for (int c = 0; c < 4; c++) {
        if (c < nc) {
            w[c] = __expf(g_mpart[(pbase + c)*64 + r] - m);
            l += w[c] * g_lpart[(pbase + c)*64 + r];
        } else w[c] = 0.f;
    }
    float inv = 1.f / l;

    #pragma unroll
    for (int j = 0; j < 4; j++) {
        float4 acc = make_float4(0.f, 0.f, 0.f, 0.f);
        #pragma unroll
        for (int c = 0; c < 4; c++) {
            if (c < nc) {
                float4 v = *reinterpret_cast<const float4*>(
                    &g_Opart[((size_t)(pbase + c)*64 + r)*64 + cb + j*4]);
                acc.x += w[c]*v.x; acc.y += w[c]*v.y;
                acc.z += w[c]*v.z; acc.w += w[c]*v.w;
            }
        }
        acc.x *= inv; acc.y *= inv; acc.z *= inv; acc.w *= inv;
        *reinterpret_cast<float4*>(&out[((size_t)b*T_ + qt*64 + r)*H_ + cb + j*4]) = acc;
    }
}

extern "C" void kernel_launch(void* const* d_in, const int* in_sizes, int n_in,
                              void* d_out, int out_size)
{
    const float* x  = (const float*)d_in[0];
    const float* Wq = (const float*)d_in[1];
    const float* Wk = (const float*)d_in[2];
    const float* Wv = (const float*)d_in[3];
    float* out = (float*)d_out;

    cudaFuncSetAttribute(proj_gemm_kernel,
                         cudaFuncAttributeMaxDynamicSharedMemorySize, SM_TOT);
    cudaFuncSetAttribute(attn_part_kernel,
                         cudaFuncAttributeMaxDynamicSharedMemorySize, ASM_TOT);

    prep_B_kernel<<<(192 * 1024) / 256, 256>>>(Wq, Wk, Wv);
    proj_gemm_kernel<<<(B_ * T_) / 128, 512, SM_TOT>>>(x);
    attn_part_kernel<<<dim3(80, B_), 128, ASM_TOT>>>();
    attn_merge_kernel<<<dim3(32, B_), 256>>>(out);
}

// round 9
// speedup vs baseline: 1.0618x; 1.0438x over previous
#include <cuda_runtime.h>
#include <cuda_bf16.h>
#include <math.h>
#include <stdint.h>

#define B_ 8
#define T_ 2048
#define C_ 1024
#define H_ 64
#define CHUNK 8          // KV tiles per attention CTA

// Q/K post-RoPE, bf16 hi/lo, row-major [B*T][64]
__device__ __align__(16) __nv_bfloat16 g_Qhi[B_*T_*H_];
__device__ __align__(16) __nv_bfloat16 g_Qlo[B_*T_*H_];
__device__ __align__(16) __nv_bfloat16 g_Khi[B_*T_*H_];
__device__ __align__(16) __nv_bfloat16 g_Klo[B_*T_*H_];
// V transposed [B][64 h][T], bf16 hi/lo
__device__ __align__(16) __nv_bfloat16 g_VThi[B_*H_*T_];
__device__ __align__(16) __nv_bfloat16 g_VTlo[B_*H_*T_];
// W split bf16 hi/lo, K-major [192][1024]
__device__ __align__(16) __nv_bfloat16 g_Bhi[192*1024];
__device__ __align__(16) __nv_bfloat16 g_Blo[192*1024];
// split-KV partials (qt >= 8 only): part = (b*32 + qt)*4 + chunk
__device__ __align__(16) float g_Opart[B_*32*4*64*64];
__device__ float g_mpart[B_*32*4*64];
__device__ float g_lpart[B_*32*4*64];

__device__ __forceinline__ uint32_t smem_u32(const void* p) {
    uint32_t a;
    asm("{ .reg .u64 t; cvta.to.shared.u64 t, %1; cvt.u32.u64 %0, t; }" : "=r"(a) : "l"(p));
    return a;
}
__device__ __forceinline__ void ldmx4(uint32_t& r0, uint32_t& r1, uint32_t& r2, uint32_t& r3,
                                      uint32_t addr) {
    asm volatile("ldmatrix.sync.aligned.m8n8.x4.shared.b16 {%0,%1,%2,%3}, [%4];"
                 : "=r"(r0), "=r"(r1), "=r"(r2), "=r"(r3) : "r"(addr));
}
__device__ __forceinline__ void mma16816(float* c,
                                         uint32_t a0, uint32_t a1, uint32_t a2, uint32_t a3,
                                         uint32_t b0, uint32_t b1) {
    asm volatile("mma.sync.aligned.m16n8k16.row.col.f32.bf16.bf16.f32 "
                 "{%0,%1,%2,%3}, {%4,%5,%6,%7}, {%8,%9}, {%0,%1,%2,%3};"
                 : "+f"(c[0]), "+f"(c[1]), "+f"(c[2]), "+f"(c[3])
                 : "r"(a0), "r"(a1), "r"(a2), "r"(a3), "r"(b0), "r"(b1));
}
__device__ __forceinline__ uint32_t bf16x2(float a, float b) {
    __nv_bfloat16 h0 = __float2bfloat16(a), h1 = __float2bfloat16(b);
    return (uint32_t)__bfloat16_as_ushort(h0) | ((uint32_t)__bfloat16_as_ushort(h1) << 16);
}
__device__ __forceinline__ float bf16lo_res(float v) {
    return v - __bfloat162float(__float2bfloat16(v));
}
#define CP_A16(dst, src) \
    asm volatile("cp.async.cg.shared.global [%0], [%1], 16;" :: "r"(dst), "l"(src))
#define CP_COMMIT() asm volatile("cp.async.commit_group;" ::: "memory")
#define CP_WAIT0()  asm volatile("cp.async.wait_group 0;" ::: "memory")

// ---------------------------------------------------------------------------
// Prep: split W{q,k,v} into bf16 hi/lo, K-major [192][1024]
// ---------------------------------------------------------------------------
__global__ __launch_bounds__(256) void prep_B_kernel(
    const float* __restrict__ Wq, const float* __restrict__ Wk, const float* __restrict__ Wv)
{
    int idx = blockIdx.x * 256 + threadIdx.x;
    int n = idx >> 10, k = idx & 1023;
    const float* W = (n < 64) ? Wq : (n < 128) ? Wk : Wv;
    float v = W[k * 64 + (n & 63)];
    __nv_bfloat16 h = __float2bfloat16(v);
    g_Bhi[idx] = h;
    g_Blo[idx] = __float2bfloat16(v - __bfloat162float(h));
}

// ---------------------------------------------------------------------------
// Projection GEMM (HMMA bf16 hi/lo split). M=128 x N=192 per CTA, 16 warps.
// ---------------------------------------------------------------------------
#define PA_STR 72
#define SM_AHI 0
#define SM_ALO (128*PA_STR*2)
#define SM_BHI (2*128*PA_STR*2)
#define SM_BLO (SM_BHI + 192*PA_STR*2)
#define SM_TOT (SM_BLO + 192*PA_STR*2)

__global__ __launch_bounds__(512) void proj_gemm_kernel(const float* __restrict__ x)
{
    extern __shared__ char smem[];
    const uint32_t sbase = smem_u32(smem);
    const int tid    = threadIdx.x;
    const int wid    = tid >> 5;
    const int lane   = tid & 31;
    const int warp_m = wid >> 2;
    const int warp_n = wid & 3;
    const int m0     = blockIdx.x * 128;

    uint32_t aOff[2], bOff[3];
    {
        int mlo = (lane >> 3) & 1, khi = (lane >> 4) & 1, r8 = lane & 7;
        #pragma unroll
        for (int mt = 0; mt < 2; mt++)
            aOff[mt] = (uint32_t)((warp_m*32 + mt*16 + mlo*8 + r8) * (PA_STR*2) + khi*16);
        #pragma unroll
        for (int p = 0; p < 3; p++)
            bOff[p] = (uint32_t)((warp_n*48 + p*16 + khi*8 + r8) * (PA_STR*2) + mlo*16);
    }

    float acc[2][6][4];
    #pragma unroll
    for (int mt = 0; mt < 2; mt++)
        #pragma unroll
        for (int nt = 0; nt < 6; nt++)
            #pragma unroll
            for (int q = 0; q < 4; q++) acc[mt][nt][q] = 0.f;

    #pragma unroll 1
    for (int c = 0; c < 16; c++) {
        const int kc = c * 64;
        if (c > 0) __syncthreads();

        #pragma unroll
        for (int it = tid; it < 2048; it += 512) {
            int r = it >> 4, q = it & 15;
            float4 f = *reinterpret_cast<const float4*>(x + (size_t)(m0 + r) * C_ + kc + q*4);
            uint32_t h0 = bf16x2(f.x, f.y), h1 = bf16x2(f.z, f.w);
            uint32_t l0 = bf16x2(bf16lo_res(f.x), bf16lo_res(f.y));
            uint32_t l1 = bf16x2(bf16lo_res(f.z), bf16lo_res(f.w));
            uint32_t off = (uint32_t)(r * (PA_STR*2) + q * 8);
            *reinterpret_cast<uint2*>(smem + SM_AHI + off) = make_uint2(h0, h1);
            *reinterpret_cast<uint2*>(smem + SM_ALO + off) = make_uint2(l0, l1);
        }
        #pragma unroll
        for (int it = tid; it < 1536; it += 512) {
            int n = it >> 3, s = it & 7;
            uint32_t off = (uint32_t)(n * (PA_STR*2) + s * 16);
            *reinterpret_cast<uint4*>(smem + SM_BHI + off) =
                *reinterpret_cast<const uint4*>(g_Bhi + (size_t)n * 1024 + kc + s*8);
            *reinterpret_cast<uint4*>(smem + SM_BLO + off) =
                *reinterpret_cast<const uint4*>(g_Blo + (size_t)n * 1024 + kc + s*8);
        }
        __syncthreads();

        #pragma unroll 1
        for (int pass = 0; pass < 3; pass++) {
            uint32_t aBase = sbase + ((pass < 2) ? SM_AHI : SM_ALO);
            uint32_t bBase = sbase + ((pass == 1) ? SM_BLO : SM_BHI);
            #pragma unroll
            for (int ks = 0; ks < 4; ks++) {
                uint32_t kb = (uint32_t)(ks * 32);
                uint32_t a[2][4];
                #pragma unroll
                for (int mt = 0; mt < 2; mt++)
                    ldmx4(a[mt][0], a[mt][1], a[mt][2], a[mt][3], aBase + aOff[mt] + kb);
                uint32_t b[6][2];
                #pragma unroll
                for (int p = 0; p < 3; p++) {
                    uint32_t r0, r1, r2, r3;
                    ldmx4(r0, r1, r2, r3, bBase + bOff[p] + kb);
                    b[p*2][0] = r0; b[p*2][1] = r1;
                    b[p*2+1][0] = r2; b[p*2+1][1] = r3;
                }
                #pragma unroll
                for (int mt = 0; mt < 2; mt++)
                    #pragma unroll
                    for (int nt = 0; nt < 6; nt++)
                        mma16816(acc[mt][nt], a[mt][0], a[mt][1], a[mt][2], a[mt][3],
                                 b[nt][0], b[nt][1]);
            }
        }
    }

    const int g  = lane >> 2;
    const int tq = lane & 3;
    #pragma unroll
    for (int mt = 0; mt < 2; mt++) {
        int row0 = m0 + warp_m*32 + mt*16 + g;
        int rows[2] = { row0, row0 + 8 };
        #pragma unroll
        for (int nt = 0; nt < 6; nt++) {
            int col = warp_n*48 + nt*8 + 2*tq;
            int mat = col >> 6;
            int col_in = col & 63;
            if (mat < 2) {
                __nv_bfloat16* dhi = (mat == 0) ? g_Qhi : g_Khi;
                __nv_bfloat16* dlo = (mat == 0) ? g_Qlo : g_Klo;
                int pi = col_in >> 1;
                float inv = powf(10000.f, -(float)pi * (1.f / 32.f));
                #pragma unroll
                for (int rg = 0; rg < 2; rg++) {
                    int t = rows[rg] & (T_ - 1);
                    float sn, cs;
                    sincosf((float)t * inv, &sn, &cs);
                    float a0 = acc[mt][nt][rg*2], a1 = acc[mt][nt][rg*2 + 1];
                    float v0 = a0*cs - a1*sn, v1 = a1*cs + a0*sn;
                    size_t base = (size_t)rows[rg] * H_ + col_in;
                    *reinterpret_cast<uint32_t*>(&dhi[base]) = bf16x2(v0, v1);
                    *reinterpret_cast<uint32_t*>(&dlo[base]) = bf16x2(bf16lo_res(v0), bf16lo_res(v1));
                }
            } else {
                #pragma unroll
                for (int rg = 0; rg < 2; rg++) {
                    int bb = rows[rg] >> 11, tt = rows[rg] & (T_ - 1);
                    #pragma unroll
                    for (int e = 0; e < 2; e++) {
                        float v = acc[mt][nt][rg*2 + e];
                        size_t idx = ((size_t)bb * H_ + (col_in + e)) * T_ + tt;
                        g_VThi[idx] = __float2bfloat16(v);
                        g_VTlo[idx] = __float2bfloat16(bf16lo_res(v));
                    }
                }
            }
        }
    }
}

// ---------------------------------------------------------------------------
// Split-KV attention partial, REGISTER-LEAN (Q reloaded per ks, K per p).
// __launch_bounds__(128, 4) -> target 4 CTAs/SM, spill-free (~110 regs).
// qt<8 (single chunk) writes final output directly via pointer arg.
// ---------------------------------------------------------------------------
#define ASTR   72
#define TILE_B (64*ASTR*2)
#define AQHI   0
#define AQLO   TILE_B
#define AKV    (2*TILE_B)
#define ASM_TOT (6*TILE_B)          // 55296

__device__ __forceinline__ void stage_kv(uint32_t sdst, int b, int kt, int tid) {
    const __nv_bfloat16* Kh = g_Khi + ((size_t)b * T_ + kt*64) * H_;
    const __nv_bfloat16* Kl = g_Klo + ((size_t)b * T_ + kt*64) * H_;
    #pragma unroll
    for (int it = tid; it < 512; it += 128) {
        int r = it >> 3, s = it & 7;
        uint32_t off = (uint32_t)(r * (ASTR*2) + s*16);
        CP_A16(sdst + off,            Kh + r*64 + s*8);
        CP_A16(sdst + TILE_B + off,   Kl + r*64 + s*8);
        size_t vsrc = ((size_t)b * H_ + r) * T_ + kt*64 + s*8;
        CP_A16(sdst + 2*TILE_B + off, g_VThi + vsrc);
        CP_A16(sdst + 3*TILE_B + off, g_VTlo + vsrc);
    }
}

__global__ __launch_bounds__(128, 4) void attn_part_kernel(float* __restrict__ out)
{
    extern __shared__ char smem[];
    const uint32_t sbase = smem_u32(smem);
    const int tid  = threadIdx.x;
    const int wid  = tid >> 5;
    const int lane = tid & 31;
    const int b    = blockIdx.y;
    const int r8   = lane & 7;
    const int mlo  = (lane >> 3) & 1;
    const int khi  = (lane >> 4) & 1;
    const int g    = lane >> 2;
    const int tq   = lane & 3;
    const float scale = 0.125f;

    int qt = 0, chunk = 0;
    {
        int bx = blockIdx.x, acc = 0;
        #pragma unroll 1
        for (int q = 0; q < 32; q++) {
            int nc = (q >> 3) + 1;
            if (bx < acc + nc) { qt = q; chunk = bx - acc; break; }
            acc += nc;
        }
    }
    const int kt0 = chunk * CHUNK;
    const int kt1 = (kt0 + CHUNK - 1 < qt) ? (kt0 + CHUNK - 1) : qt;

    const uint32_t aRowOff = (uint32_t)((wid*16 + mlo*8 + r8) * (ASTR*2) + khi*16);
    uint32_t bRowOff[4];
    #pragma unroll
    for (int p = 0; p < 4; p++)
        bRowOff[p] = (uint32_t)((p*16 + khi*8 + r8) * (ASTR*2) + mlo*16);

    {
        const __nv_bfloat16* Qh = g_Qhi + ((size_t)b * T_ + qt*64) * H_;
        const __nv_bfloat16* Ql = g_Qlo + ((size_t)b * T_ + qt*64) * H_;
        #pragma unroll
        for (int it = tid; it < 512; it += 128) {
            int r = it >> 3, s = it & 7;
            uint32_t off = (uint32_t)(r * (ASTR*2) + s*16);
            CP_A16(sbase + AQHI + off, Qh + r*64 + s*8);
            CP_A16(sbase + AQLO + off, Ql + r*64 + s*8);
        }
        stage_kv(sbase + AKV, b, kt0, tid);
        CP_COMMIT();
    }
    CP_WAIT0();
    __syncthreads();

    float m0r = -1e30f, m1r = -1e30f, l0 = 0.f, l1 = 0.f;
    float o[8][4];
    #pragma unroll
    for (int nt = 0; nt < 8; nt++)
        #pragma unroll
        for (int q = 0; q < 4; q++) o[nt][q] = 0.f;

    #pragma unroll 1
    for (int kt = kt0; kt <= kt1; kt++) {
        const uint32_t kvb = sbase + AKV;

        float s_[8][4];
        #pragma unroll
        for (int nt = 0; nt < 8; nt++)
            #pragma unroll
            for (int q = 0; q < 4; q++) s_[nt][q] = 0.f;

        #pragma unroll
        for (int ks = 0; ks < 4; ks++) {
            uint32_t kb = (uint32_t)(ks * 32);
            uint32_t qh0, qh1, qh2, qh3, ql0, ql1, ql2, ql3;
            ldmx4(qh0, qh1, qh2, qh3, sbase + AQHI + aRowOff + kb);
            ldmx4(ql0, ql1, ql2, ql3, sbase + AQLO + aRowOff + kb);
            #pragma unroll
            for (int p = 0; p < 4; p++) {
                uint32_t kh0, kh1, kh2, kh3, kl0, kl1, kl2, kl3;
                ldmx4(kh0, kh1, kh2, kh3, kvb + bRowOff[p] + kb);
                ldmx4(kl0, kl1, kl2, kl3, kvb + TILE_B + bRowOff[p] + kb);
                mma16816(s_[2*p],   qh0, qh1, qh2, qh3, kh0, kh1);
                mma16816(s_[2*p+1], qh0, qh1, qh2, qh3, kh2, kh3);
                mma16816(s_[2*p],   qh0, qh1, qh2, qh3, kl0, kl1);
                mma16816(s_[2*p+1], qh0, qh1, qh2, qh3, kl2, kl3);
                mma16816(s_[2*p],   ql0, ql1, ql2, ql3, kh0, kh1);
                mma16816(s_[2*p+1], ql0, ql1, ql2, ql3, kh2, kh3);
            }
        }

        #pragma unroll
        for (int nt = 0; nt < 8; nt++)
            #pragma unroll
            for (int q = 0; q < 4; q++) s_[nt][q] *= scale;
        if (kt == qt) {
            int qr0 = qt*64 + wid*16 + g;
            #pragma unroll
            for (int nt = 0; nt < 8; nt++) {
                int kc0 = kt*64 + nt*8 + 2*tq;
                if (kc0     > qr0)     s_[nt][0] = -1e30f;
                if (kc0 + 1 > qr0)     s_[nt][1] = -1e30f;
                if (kc0     > qr0 + 8) s_[nt][2] = -1e30f;
                if (kc0 + 1 > qr0 + 8) s_[nt][3] = -1e30f;
            }
        }

        float mx0 = -1e30f, mx1 = -1e30f;
        #pragma unroll
        for (int nt = 0; nt < 8; nt++) {
            mx0 = fmaxf(mx0, fmaxf(s_[nt][0], s_[nt][1]));
            mx1 = fmaxf(mx1, fmaxf(s_[nt][2], s_[nt][3]));
        }
        mx0 = fmaxf(mx0, __shfl_xor_sync(0xffffffffu, mx0, 1));
        mx0 = fmaxf(mx0, __shfl_xor_sync(0xffffffffu, mx0, 2));
        mx1 = fmaxf(mx1, __shfl_xor_sync(0xffffffffu, mx1, 1));
        mx1 = fmaxf(mx1, __shfl_xor_sync(0xffffffffu, mx1, 2));
        float mn0 = fmaxf(m0r, mx0), mn1 = fmaxf(m1r, mx1);
        float al0 = __expf(m0r - mn0), al1 = __expf(m1r - mn1);
        float rs0 = 0.f, rs1 = 0.f;
        #pragma unroll
        for (int nt = 0; nt < 8; nt++) {
            s_[nt][0] = __expf(s_[nt][0] - mn0);
            s_[nt][1] = __expf(s_[nt][1] - mn0);
            s_[nt][2] = __expf(s_[nt][2] - mn1);
            s_[nt][3] = __expf(s_[nt][3] - mn1);
            rs0 += s_[nt][0] + s_[nt][1];
            rs1 += s_[nt][2] + s_[nt][3];
        }
        rs0 += __shfl_xor_sync(0xffffffffu, rs0, 1);
        rs0 += __shfl_xor_sync(0xffffffffu, rs0, 2);
        rs1 += __shfl_xor_sync(0xffffffffu, rs1, 1);
        rs1 += __shfl_xor_sync(0xffffffffu, rs1, 2);
        l0 = l0 * al0 + rs0;  l1 = l1 * al1 + rs1;
        m0r = mn0;  m1r = mn1;
        #pragma unroll
        for (int nt = 0; nt < 8; nt++) {
            o[nt][0] *= al0; o[nt][1] *= al0;
            o[nt][2] *= al1; o[nt][3] *= al1;
        }

        #pragma unroll
        for (int kk = 0; kk < 4; kk++) {
            uint32_t ah[4], al_[4];
            ah[0] = bf16x2(s_[2*kk][0],   s_[2*kk][1]);
            ah[1] = bf16x2(s_[2*kk][2],   s_[2*kk][3]);
            ah[2] = bf16x2(s_[2*kk+1][0], s_[2*kk+1][1]);
            ah[3] = bf16x2(s_[2*kk+1][2], s_[2*kk+1][3]);
            al_[0] = bf16x2(bf16lo_res(s_[2*kk][0]),   bf16lo_res(s_[2*kk][1]));
            al_[1] = bf16x2(bf16lo_res(s_[2*kk][2]),   bf16lo_res(s_[2*kk][3]));
            al_[2] = bf16x2(bf16lo_res(s_[2*kk+1][0]), bf16lo_res(s_[2*kk+1][1]));
            al_[3] = bf16x2(bf16lo_res(s_[2*kk+1][2]), bf16lo_res(s_[2*kk+1][3]));
            uint32_t kb = (uint32_t)(kk * 32);
            #pragma unroll
            for (int p = 0; p < 4; p++) {
                uint32_t vh0, vh1, vh2, vh3, vl0, vl1, vl2, vl3;
                ldmx4(vh0, vh1, vh2, vh3, kvb + 2*TILE_B + bRowOff[p] + kb);
                ldmx4(vl0, vl1, vl2, vl3, kvb + 3*TILE_B + bRowOff[p] + kb);
                mma16816(o[2*p],   ah[0], ah[1], ah[2], ah[3], vh0, vh1);
                mma16816(o[2*p+1], ah[0], ah[1], ah[2], ah[3], vh2, vh3);
                mma16816(o[2*p],   ah[0], ah[1], ah[2], ah[3], vl0, vl1);
                mma16816(o[2*p+1], ah[0], ah[1], ah[2], ah[3], vl2, vl3);
                mma16816(o[2*p],   al_[0], al_[1], al_[2], al_[3], vh0, vh1);
                mma16816(o[2*p+1], al_[0], al_[1], al_[2], al_[3], vh2, vh3);
            }
        }

        __syncthreads();
        if (kt < kt1) {
            stage_kv(sbase + AKV, b, kt + 1, tid);
            CP_COMMIT();
            CP_WAIT0();
            __syncthreads();
        }
    }

    const int row0 = wid*16 + g;
    if (qt < 8) {
        float rc0 = 1.f / l0, rc1 = 1.f / l1;
        #pragma unroll
        for (int nt = 0; nt < 8; nt++) {
            int col = nt*8 + 2*tq;
            *reinterpret_cast<float2*>(&out[((size_t)b*T_ + qt*64 + row0) * H_ + col]) =
                make_float2(o[nt][0]*rc0, o[nt][1]*rc0);
            *reinterpret_cast<float2*>(&out[((size_t)b*T_ + qt*64 + row0 + 8) * H_ + col]) =
                make_float2(o[nt][2]*rc1, o[nt][3]*rc1);
        }
    } else {
        const int part = (b*32 + qt)*4 + chunk;
        float* Op = g_Opart + (size_t)part * 64 * 64;
        #pragma unroll
        for (int nt = 0; nt < 8; nt++) {
            int col = nt*8 + 2*tq;
            *reinterpret_cast<float2*>(&Op[(row0)     * 64 + col]) = make_float2(o[nt][0], o[nt][1]);
            *reinterpret_cast<float2*>(&Op[(row0 + 8) * 64 + col]) = make_float2(o[nt][2], o[nt][3]);
        }
        if (tq == 0) {
            g_mpart[part*64 + row0]     = m0r;
            g_mpart[part*64 + row0 + 8] = m1r;
            g_lpart[part*64 + row0]     = l0;
            g_lpart[part*64 + row0 + 8] = l1;
        }
    }
}

// ---------------------------------------------------------------------------
// Merge: combine chunk partials per (b, qt) for qt >= 8 only.
// ---------------------------------------------------------------------------
__global__ __launch_bounds__(256) void attn_merge_kernel(float* __restrict__ out)
{
    const int qt = blockIdx.x + 8, b = blockIdx.y;
    const int nc = (qt >> 3) + 1;
    const int r  = threadIdx.x >> 2;
    const int cb = (threadIdx.x & 3) * 16;
    const int pbase = (b*32 + qt)*4;

    float m = -1e30f;
    #pragma unroll
    for (int c = 0; c < 4; c++)
        if (c < nc) m = fmaxf(m, g_mpart[(pbase + c)*64 + r]);
    float w[4];
    float l = 0.f;
    #pragma unroll
    for (int c = 0; c < 4; c++) {
        if (c < nc) {
            w[c] = __expf(g_mpart[(pbase + c)*64 + r] - m);
            l += w[c] * g_lpart[(pbase + c)*64 + r];
        } else w[c] = 0.f;
    }
    float inv = 1.f / l;

    #pragma unroll
    for (int j = 0; j < 4; j++) {
        float4 acc = make_float4(0.f, 0.f, 0.f, 0.f);
        #pragma unroll
        for (int c = 0; c < 4; c++) {
            if (c < nc) {
                float4 v = *reinterpret_cast<const float4*>(
                    &g_Opart[((size_t)(pbase + c)*64 + r)*64 + cb + j*4]);
                acc.x += w[c]*v.x; acc.y += w[c]*v.y;
                acc.z += w[c]*v.z; acc.w += w[c]*v.w;
            }
        }
        acc.x *= inv; acc.y *= inv; acc.z *= inv; acc.w *= inv;
        *reinterpret_cast<float4*>(&out[((size_t)b*T_ + qt*64 + r)*H_ + cb + j*4]) = acc;
    }
}

extern "C" void kernel_launch(void* const* d_in, const int* in_sizes, int n_in,
                              void* d_out, int out_size)
{
    const float* x  = (const float*)d_in[0];
    const float* Wq = (const float*)d_in[1];
    const float* Wk = (const float*)d_in[2];
    const float* Wv = (const float*)d_in[3];
    float* out = (float*)d_out;

    cudaFuncSetAttribute(proj_gemm_kernel,
                         cudaFuncAttributeMaxDynamicSharedMemorySize, SM_TOT);
    cudaFuncSetAttribute(attn_part_kernel,
                         cudaFuncAttributeMaxDynamicSharedMemorySize, ASM_TOT);

    prep_B_kernel<<<(192 * 1024) / 256, 256>>>(Wq, Wk, Wv);
    proj_gemm_kernel<<<(B_ * T_) / 128, 512, SM_TOT>>>(x);
    attn_part_kernel<<<dim3(80, B_), 128, ASM_TOT>>>(out);
    attn_merge_kernel<<<dim3(24, B_), 256>>>(out);
}

// round 10
// speedup vs baseline: 1.1431x; 1.0765x over previous
#include <cuda_runtime.h>
#include <cuda_bf16.h>
#include <cuda_fp16.h>
#include <math.h>
#include <stdint.h>

#define B_ 8
#define T_ 2048
#define C_ 1024
#define H_ 64
#define CHUNK 8          // KV tiles per attention CTA

// Q/K post-RoPE, fp16 hi/lo, row-major [B*T][64]
__device__ __align__(16) __half g_Qhi[B_*T_*H_];
__device__ __align__(16) __half g_Qlo[B_*T_*H_];
__device__ __align__(16) __half g_Khi[B_*T_*H_];
__device__ __align__(16) __half g_Klo[B_*T_*H_];
// V transposed [B][64 h][T], fp16 hi/lo
__device__ __align__(16) __half g_VThi[B_*H_*T_];
__device__ __align__(16) __half g_VTlo[B_*H_*T_];
// W split bf16 hi/lo, K-major [192][1024]  (proj GEMM stays bf16)
__device__ __align__(16) __nv_bfloat16 g_Bhi[192*1024];
__device__ __align__(16) __nv_bfloat16 g_Blo[192*1024];
// split-KV partials (qt >= 8 only): part = (b*32 + qt)*4 + chunk
__device__ __align__(16) float g_Opart[B_*32*4*64*64];
__device__ float g_mpart[B_*32*4*64];
__device__ float g_lpart[B_*32*4*64];

__device__ __forceinline__ uint32_t smem_u32(const void* p) {
    uint32_t a;
    asm("{ .reg .u64 t; cvta.to.shared.u64 t, %1; cvt.u32.u64 %0, t; }" : "=r"(a) : "l"(p));
    return a;
}
__device__ __forceinline__ void ldmx4(uint32_t& r0, uint32_t& r1, uint32_t& r2, uint32_t& r3,
                                      uint32_t addr) {
    asm volatile("ldmatrix.sync.aligned.m8n8.x4.shared.b16 {%0,%1,%2,%3}, [%4];"
                 : "=r"(r0), "=r"(r1), "=r"(r2), "=r"(r3) : "r"(addr));
}
// bf16 MMA (proj)
__device__ __forceinline__ void mma_bf16(float* c,
                                         uint32_t a0, uint32_t a1, uint32_t a2, uint32_t a3,
                                         uint32_t b0, uint32_t b1) {
    asm volatile("mma.sync.aligned.m16n8k16.row.col.f32.bf16.bf16.f32 "
                 "{%0,%1,%2,%3}, {%4,%5,%6,%7}, {%8,%9}, {%0,%1,%2,%3};"
                 : "+f"(c[0]), "+f"(c[1]), "+f"(c[2]), "+f"(c[3])
                 : "r"(a0), "r"(a1), "r"(a2), "r"(a3), "r"(b0), "r"(b1));
}
// fp16 MMA (attention)
__device__ __forceinline__ void mma_f16(float* c,
                                        uint32_t a0, uint32_t a1, uint32_t a2, uint32_t a3,
                                        uint32_t b0, uint32_t b1) {
    asm volatile("mma.sync.aligned.m16n8k16.row.col.f32.f16.f16.f32 "
                 "{%0,%1,%2,%3}, {%4,%5,%6,%7}, {%8,%9}, {%0,%1,%2,%3};"
                 : "+f"(c[0]), "+f"(c[1]), "+f"(c[2]), "+f"(c[3])
                 : "r"(a0), "r"(a1), "r"(a2), "r"(a3), "r"(b0), "r"(b1));
}
__device__ __forceinline__ uint32_t bf16x2(float a, float b) {
    __nv_bfloat16 h0 = __float2bfloat16(a), h1 = __float2bfloat16(b);
    return (uint32_t)__bfloat16_as_ushort(h0) | ((uint32_t)__bfloat16_as_ushort(h1) << 16);
}
__device__ __forceinline__ float bf16lo_res(float v) {
    return v - __bfloat162float(__float2bfloat16(v));
}
__device__ __forceinline__ uint32_t h2pack(float a, float b) {
    __half2 h = __floats2half2_rn(a, b);
    return *reinterpret_cast<uint32_t*>(&h);
}
__device__ __forceinline__ float h_lo_res(float v) {
    return v - __half2float(__float2half_rn(v));
}
#define CP_A16(dst, src) \
    asm volatile("cp.async.cg.shared.global [%0], [%1], 16;" :: "r"(dst), "l"(src))
#define CP_COMMIT() asm volatile("cp.async.commit_group;" ::: "memory")
#define CP_WAIT0()  asm volatile("cp.async.wait_group 0;" ::: "memory")

// ---------------------------------------------------------------------------
// Prep: split W{q,k,v} into bf16 hi/lo, K-major [192][1024]
// ---------------------------------------------------------------------------
__global__ __launch_bounds__(256) void prep_B_kernel(
    const float* __restrict__ Wq, const float* __restrict__ Wk, const float* __restrict__ Wv)
{
    int idx = blockIdx.x * 256 + threadIdx.x;
    int n = idx >> 10, k = idx & 1023;
    const float* W = (n < 64) ? Wq : (n < 128) ? Wk : Wv;
    float v = W[k * 64 + (n & 63)];
    __nv_bfloat16 h = __float2bfloat16(v);
    g_Bhi[idx] = h;
    g_Blo[idx] = __float2bfloat16(v - __bfloat162float(h));
}

// ---------------------------------------------------------------------------
// Projection GEMM (HMMA bf16 hi/lo split). M=128 x N=192 per CTA, 16 warps.
// Epilogue: RoPE, then write Q/K fp16 hi/lo row-major; V fp16 hi/lo transposed.
// ---------------------------------------------------------------------------
#define PA_STR 72
#define SM_AHI 0
#define SM_ALO (128*PA_STR*2)
#define SM_BHI (2*128*PA_STR*2)
#define SM_BLO (SM_BHI + 192*PA_STR*2)
#define SM_TOT (SM_BLO + 192*PA_STR*2)

__global__ __launch_bounds__(512) void proj_gemm_kernel(const float* __restrict__ x)
{
    extern __shared__ char smem[];
    const uint32_t sbase = smem_u32(smem);
    const int tid    = threadIdx.x;
    const int wid    = tid >> 5;
    const int lane   = tid & 31;
    const int warp_m = wid >> 2;
    const int warp_n = wid & 3;
    const int m0     = blockIdx.x * 128;

    uint32_t aOff[2], bOff[3];
    {
        int mlo = (lane >> 3) & 1, khi = (lane >> 4) & 1, r8 = lane & 7;
        #pragma unroll
        for (int mt = 0; mt < 2; mt++)
            aOff[mt] = (uint32_t)((warp_m*32 + mt*16 + mlo*8 + r8) * (PA_STR*2) + khi*16);
        #pragma unroll
        for (int p = 0; p < 3; p++)
            bOff[p] = (uint32_t)((warp_n*48 + p*16 + khi*8 + r8) * (PA_STR*2) + mlo*16);
    }

    float acc[2][6][4];
    #pragma unroll
    for (int mt = 0; mt < 2; mt++)
        #pragma unroll
        for (int nt = 0; nt < 6; nt++)
            #pragma unroll
            for (int q = 0; q < 4; q++) acc[mt][nt][q] = 0.f;

    #pragma unroll 1
    for (int c = 0; c < 16; c++) {
        const int kc = c * 64;
        if (c > 0) __syncthreads();

        #pragma unroll
        for (int it = tid; it < 2048; it += 512) {
            int r = it >> 4, q = it & 15;
            float4 f = *reinterpret_cast<const float4*>(x + (size_t)(m0 + r) * C_ + kc + q*4);
            uint32_t h0 = bf16x2(f.x, f.y), h1 = bf16x2(f.z, f.w);
            uint32_t l0 = bf16x2(bf16lo_res(f.x), bf16lo_res(f.y));
            uint32_t l1 = bf16x2(bf16lo_res(f.z), bf16lo_res(f.w));
            uint32_t off = (uint32_t)(r * (PA_STR*2) + q * 8);
            *reinterpret_cast<uint2*>(smem + SM_AHI + off) = make_uint2(h0, h1);
            *reinterpret_cast<uint2*>(smem + SM_ALO + off) = make_uint2(l0, l1);
        }
        #pragma unroll
        for (int it = tid; it < 1536; it += 512) {
            int n = it >> 3, s = it & 7;
            uint32_t off = (uint32_t)(n * (PA_STR*2) + s * 16);
            *reinterpret_cast<uint4*>(smem + SM_BHI + off) =
                *reinterpret_cast<const uint4*>(g_Bhi + (size_t)n * 1024 + kc + s*8);
            *reinterpret_cast<uint4*>(smem + SM_BLO + off) =
                *reinterpret_cast<const uint4*>(g_Blo + (size_t)n * 1024 + kc + s*8);
        }
        __syncthreads();

        #pragma unroll 1
        for (int pass = 0; pass < 3; pass++) {
            uint32_t aBase = sbase + ((pass < 2) ? SM_AHI : SM_ALO);
            uint32_t bBase = sbase + ((pass == 1) ? SM_BLO : SM_BHI);
            #pragma unroll
            for (int ks = 0; ks < 4; ks++) {
                uint32_t kb = (uint32_t)(ks * 32);
                uint32_t a[2][4];
                #pragma unroll
                for (int mt = 0; mt < 2; mt++)
                    ldmx4(a[mt][0], a[mt][1], a[mt][2], a[mt][3], aBase + aOff[mt] + kb);
                uint32_t b[6][2];
                #pragma unroll
                for (int p = 0; p < 3; p++) {
                    uint32_t r0, r1, r2, r3;
                    ldmx4(r0, r1, r2, r3, bBase + bOff[p] + kb);
                    b[p*2][0] = r0; b[p*2][1] = r1;
                    b[p*2+1][0] = r2; b[p*2+1][1] = r3;
                }
                #pragma unroll
                for (int mt = 0; mt < 2; mt++)
                    #pragma unroll
                    for (int nt = 0; nt < 6; nt++)
                        mma_bf16(acc[mt][nt], a[mt][0], a[mt][1], a[mt][2], a[mt][3],
                                 b[nt][0], b[nt][1]);
            }
        }
    }

    const int g  = lane >> 2;
    const int tq = lane & 3;
    #pragma unroll
    for (int mt = 0; mt < 2; mt++) {
        int row0 = m0 + warp_m*32 + mt*16 + g;
        int rows[2] = { row0, row0 + 8 };
        #pragma unroll
        for (int nt = 0; nt < 6; nt++) {
            int col = warp_n*48 + nt*8 + 2*tq;
            int mat = col >> 6;
            int col_in = col & 63;
            if (mat < 2) {
                __half* dhi = (mat == 0) ? g_Qhi : g_Khi;
                __half* dlo = (mat == 0) ? g_Qlo : g_Klo;
                int pi = col_in >> 1;
                float inv = powf(10000.f, -(float)pi * (1.f / 32.f));
                #pragma unroll
                for (int rg = 0; rg < 2; rg++) {
                    int t = rows[rg] & (T_ - 1);
                    float sn, cs;
                    sincosf((float)t * inv, &sn, &cs);
                    float a0 = acc[mt][nt][rg*2], a1 = acc[mt][nt][rg*2 + 1];
                    float v0 = a0*cs - a1*sn, v1 = a1*cs + a0*sn;
                    size_t base = (size_t)rows[rg] * H_ + col_in;
                    *reinterpret_cast<uint32_t*>(&dhi[base]) = h2pack(v0, v1);
                    *reinterpret_cast<uint32_t*>(&dlo[base]) = h2pack(h_lo_res(v0), h_lo_res(v1));
                }
            } else {
                #pragma unroll
                for (int rg = 0; rg < 2; rg++) {
                    int bb = rows[rg] >> 11, tt = rows[rg] & (T_ - 1);
                    #pragma unroll
                    for (int e = 0; e < 2; e++) {
                        float v = acc[mt][nt][rg*2 + e];
                        size_t idx = ((size_t)bb * H_ + (col_in + e)) * T_ + tt;
                        g_VThi[idx] = __float2half_rn(v);
                        g_VTlo[idx] = __float2half_rn(h_lo_res(v));
                    }
                }
            }
        }
    }
}

// ---------------------------------------------------------------------------
// Split-KV attention partial (fp16 split): S = Qh*Kh + Qh*Kl + Ql*Kh (3 passes,
// error ~2^-21); PV = Ph*Vh + Ph*Vl (2 passes; Plo*V dropped, ~1.5e-4 rel).
// Register-lean, __launch_bounds__(128, 4). qt<8 writes output directly.
// ---------------------------------------------------------------------------
#define ASTR   72
#define TILE_B (64*ASTR*2)
#define AQHI   0
#define AQLO   TILE_B
#define AKV    (2*TILE_B)
#define ASM_TOT (6*TILE_B)          // 55296

__device__ __forceinline__ void stage_kv(uint32_t sdst, int b, int kt, int tid) {
    const __half* Kh = g_Khi + ((size_t)b * T_ + kt*64) * H_;
    const __half* Kl = g_Klo + ((size_t)b * T_ + kt*64) * H_;
    #pragma unroll
    for (int it = tid; it < 512; it += 128) {
        int r = it >> 3, s = it & 7;
        uint32_t off = (uint32_t)(r * (ASTR*2) + s*16);
        CP_A16(sdst + off,            Kh + r*64 + s*8);
        CP_A16(sdst + TILE_B + off,   Kl + r*64 + s*8);
        size_t vsrc = ((size_t)b * H_ + r) * T_ + kt*64 + s*8;
        CP_A16(sdst + 2*TILE_B + off, g_VThi + vsrc);
        CP_A16(sdst + 3*TILE_B + off, g_VTlo + vsrc);
    }
}

__global__ __launch_bounds__(128, 4) void attn_part_kernel(float* __restrict__ out)
{
    extern __shared__ char smem[];
    const uint32_t sbase = smem_u32(smem);
    const int tid  = threadIdx.x;
    const int wid  = tid >> 5;
    const int lane = tid & 31;
    const int b    = blockIdx.y;
    const int r8   = lane & 7;
    const int mlo  = (lane >> 3) & 1;
    const int khi  = (lane >> 4) & 1;
    const int g    = lane >> 2;
    const int tq   = lane & 3;
    const float scale = 0.125f;

    int qt = 0, chunk = 0;
    {
        int bx = blockIdx.x, acc = 0;
        #pragma unroll 1
        for (int q = 0; q < 32; q++) {
            int nc = (q >> 3) + 1;
            if (bx < acc + nc) { qt = q; chunk = bx - acc; break; }
            acc += nc;
        }
    }
    const int kt0 = chunk * CHUNK;
    const int kt1 = (kt0 + CHUNK - 1 < qt) ? (kt0 + CHUNK - 1) : qt;

    const uint32_t aRowOff = (uint32_t)((wid*16 + mlo*8 + r8) * (ASTR*2) + khi*16);
    uint32_t bRowOff[4];
    #pragma unroll
    for (int p = 0; p < 4; p++)
        bRowOff[p] = (uint32_t)((p*16 + khi*8 + r8) * (ASTR*2) + mlo*16);

    {
        const __half* Qh = g_Qhi + ((size_t)b * T_ + qt*64) * H_;
        const __half* Ql = g_Qlo + ((size_t)b * T_ + qt*64) * H_;
        #pragma unroll
        for (int it = tid; it < 512; it += 128) {
            int r = it >> 3, s = it & 7;
            uint32_t off = (uint32_t)(r * (ASTR*2) + s*16);
            CP_A16(sbase + AQHI + off, Qh + r*64 + s*8);
            CP_A16(sbase + AQLO + off, Ql + r*64 + s*8);
        }
        stage_kv(sbase + AKV, b, kt0, tid);
        CP_COMMIT();
    }
    CP_WAIT0();
    __syncthreads();

    float m0r = -1e30f, m1r = -1e30f, l0 = 0.f, l1 = 0.f;
    float o[8][4];
    #pragma unroll
    for (int nt = 0; nt < 8; nt++)
        #pragma unroll
        for (int q = 0; q < 4; q++) o[nt][q] = 0.f;

    #pragma unroll 1
    for (int kt = kt0; kt <= kt1; kt++) {
        const uint32_t kvb = sbase + AKV;

        float s_[8][4];
        #pragma unroll
        for (int nt = 0; nt < 8; nt++)
            #pragma unroll
            for (int q = 0; q < 4; q++) s_[nt][q] = 0.f;

        #pragma unroll
        for (int ks = 0; ks < 4; ks++) {
            uint32_t kb = (uint32_t)(ks * 32);
            uint32_t qh0, qh1, qh2, qh3, ql0, ql1, ql2, ql3;
            ldmx4(qh0, qh1, qh2, qh3, sbase + AQHI + aRowOff + kb);
            ldmx4(ql0, ql1, ql2, ql3, sbase + AQLO + aRowOff + kb);
            #pragma unroll
            for (int p = 0; p < 4; p++) {
                uint32_t kh0, kh1, kh2, kh3, kl0, kl1, kl2, kl3;
                ldmx4(kh0, kh1, kh2, kh3, kvb + bRowOff[p] + kb);
                ldmx4(kl0, kl1, kl2, kl3, kvb + TILE_B + bRowOff[p] + kb);
                mma_f16(s_[2*p],   qh0, qh1, qh2, qh3, kh0, kh1);
                mma_f16(s_[2*p+1], qh0, qh1, qh2, qh3, kh2, kh3);
                mma_f16(s_[2*p],   qh0, qh1, qh2, qh3, kl0, kl1);
                mma_f16(s_[2*p+1], qh0, qh1, qh2, qh3, kl2, kl3);
                mma_f16(s_[2*p],   ql0, ql1, ql2, ql3, kh0, kh1);
                mma_f16(s_[2*p+1], ql0, ql1, ql2, ql3, kh2, kh3);
            }
        }

        #pragma unroll
        for (int nt = 0; nt < 8; nt++)
            #pragma unroll
            for (int q = 0; q < 4; q++) s_[nt][q] *= scale;
        if (kt == qt) {
            int qr0 = qt*64 + wid*16 + g;
            #pragma unroll
            for (int nt = 0; nt < 8; nt++) {
                int kc0 = kt*64 + nt*8 + 2*tq;
                if (kc0     > qr0)     s_[nt][0] = -1e30f;
                if (kc0 + 1 > qr0)     s_[nt][1] = -1e30f;
                if (kc0     > qr0 + 8) s_[nt][2] = -1e30f;
                if (kc0 + 1 > qr0 + 8) s_[nt][3] = -1e30f;
            }
        }

        float mx0 = -1e30f, mx1 = -1e30f;
        #pragma unroll
        for (int nt = 0; nt < 8; nt++) {
            mx0 = fmaxf(mx0, fmaxf(s_[nt][0], s_[nt][1]));
            mx1 = fmaxf(mx1, fmaxf(s_[nt][2], s_[nt][3]));
        }
        mx0 = fmaxf(mx0, __shfl_xor_sync(0xffffffffu, mx0, 1));
        mx0 = fmaxf(mx0, __shfl_xor_sync(0xffffffffu, mx0, 2));
        mx1 = fmaxf(mx1, __shfl_xor_sync(0xffffffffu, mx1, 1));
        mx1 = fmaxf(mx1, __shfl_xor_sync(0xffffffffu, mx1, 2));
        float mn0 = fmaxf(m0r, mx0), mn1 = fmaxf(m1r, mx1);
        float al0 = __expf(m0r - mn0), al1 = __expf(m1r - mn1);
        float rs0 = 0.f, rs1 = 0.f;
        #pragma unroll
        for (int nt = 0; nt < 8; nt++) {
            s_[nt][0] = __expf(s_[nt][0] - mn0);
            s_[nt][1] = __expf(s_[nt][1] - mn0);
            s_[nt][2] = __expf(s_[nt][2] - mn1);
            s_[nt][3] = __expf(s_[nt][3] - mn1);
            rs0 += s_[nt][0] + s_[nt][1];
            rs1 += s_[nt][2] + s_[nt][3];
        }
        rs0 += __shfl_xor_sync(0xffffffffu, rs0, 1);
        rs0 += __shfl_xor_sync(0xffffffffu, rs0, 2);
        rs1 += __shfl_xor_sync(0xffffffffu, rs1, 1);
        rs1 += __shfl_xor_sync(0xffffffffu, rs1, 2);
        l0 = l0 * al0 + rs0;  l1 = l1 * al1 + rs1;
        m0r = mn0;  m1r = mn1;
        #pragma unroll
        for (int nt = 0; nt < 8; nt++) {
            o[nt][0] *= al0; o[nt][1] *= al0;
            o[nt][2] *= al1; o[nt][3] *= al1;
        }

        // ---- O += P V  (fp16 P, 2 passes: Ph*Vh + Ph*Vl) ----
        #pragma unroll
        for (int kk = 0; kk < 4; kk++) {
            uint32_t ah[4];
            ah[0] = h2pack(s_[2*kk][0],   s_[2*kk][1]);
            ah[1] = h2pack(s_[2*kk][2],   s_[2*kk][3]);
            ah[2] = h2pack(s_[2*kk+1][0], s_[2*kk+1][1]);
            ah[3] = h2pack(s_[2*kk+1][2], s_[2*kk+1][3]);
            uint32_t kb = (uint32_t)(kk * 32);
            #pragma unroll
            for (int p = 0; p < 4; p++) {
                uint32_t vh0, vh1, vh2, vh3, vl0, vl1, vl2, vl3;
                ldmx4(vh0, vh1, vh2, vh3, kvb + 2*TILE_B + bRowOff[p] + kb);
                ldmx4(vl0, vl1, vl2, vl3, kvb + 3*TILE_B + bRowOff[p] + kb);
                mma_f16(o[2*p],   ah[0], ah[1], ah[2], ah[3], vh0, vh1);
                mma_f16(o[2*p+1], ah[0], ah[1], ah[2], ah[3], vh2, vh3);
                mma_f16(o[2*p],   ah[0], ah[1], ah[2], ah[3], vl0, vl1);
                mma_f16(o[2*p+1], ah[0], ah[1], ah[2], ah[3], vl2, vl3);
            }
        }

        __syncthreads();
        if (kt < kt1) {
            stage_kv(sbase + AKV, b, kt + 1, tid);
            CP_COMMIT();
            CP_WAIT0();
            __syncthreads();
        }
    }

    const int row0 = wid*16 + g;
    if (qt < 8) {
        float rc0 = 1.f / l0, rc1 = 1.f / l1;
        #pragma unroll
        for (int nt = 0; nt < 8; nt++) {
            int col = nt*8 + 2*tq;
            *reinterpret_cast<float2*>(&out[((size_t)b*T_ + qt*64 + row0) * H_ + col]) =
                make_float2(o[nt][0]*rc0, o[nt][1]*rc0);
            *reinterpret_cast<float2*>(&out[((size_t)b*T_ + qt*64 + row0 + 8) * H_ + col]) =
                make_float2(o[nt][2]*rc1, o[nt][3]*rc1);
        }
    } else {
        const int part = (b*32 + qt)*4 + chunk;
        float* Op = g_Opart + (size_t)part * 64 * 64;
        #pragma unroll
        for (int nt = 0; nt < 8; nt++) {
            int col = nt*8 + 2*tq;
            *reinterpret_cast<float2*>(&Op[(row0)     * 64 + col]) = make_float2(o[nt][0], o[nt][1]);
            *reinterpret_cast<float2*>(&Op[(row0 + 8) * 64 + col]) = make_float2(o[nt][2], o[nt][3]);
        }
        if (tq == 0) {
            g_mpart[part*64 + row0]     = m0r;
            g_mpart[part*64 + row0 + 8] = m1r;
            g_lpart[part*64 + row0]     = l0;
            g_lpart[part*64 + row0 + 8] = l1;
        }
    }
}

// ---------------------------------------------------------------------------
// Merge: combine chunk partials per (b, qt) for qt >= 8; 4 row-group blocks
// per (b, qt) for 4x the parallelism of the previous version.
// ---------------------------------------------------------------------------
__global__ __launch_bounds__(256) void attn_merge_kernel(float* __restrict__ out)
{
    const int qt = blockIdx.x + 8, b = blockIdx.y;
    const int nc = (qt >> 3) + 1;
    const int r  = (int)blockIdx.z * 16 + (threadIdx.x >> 4);  // 0..63
    const int cb = (threadIdx.x & 15) * 4;
    const int pbase = (b*32 + qt)*4;

    float m = -1e30f;
    #pragma unroll
    for (int c = 0; c < 4; c++)
        if (c < nc) m = fmaxf(m, g_mpart[(pbase + c)*64 + r]);
    float w[4];
    float l = 0.f;
    #pragma unroll
    for (int c = 0; c < 4; c++) {
        if (c < nc) {
            w[c] = __expf(g_mpart[(pbase + c)*64 + r] - m);
            l += w[c] * g_lpart[(pbase + c)*64 + r];
        } else w[c] = 0.f;
    }
    float inv = 1.f / l;

    float4 acc = make_float4(0.f, 0.f, 0.f, 0.f);
    #pragma unroll
    for (int c = 0; c < 4; c++) {
        if (c < nc) {
            float4 v = *reinterpret_cast<const float4*>(
                &g_Opart[((size_t)(pbase + c)*64 + r)*64 + cb]);
            acc.x += w[c]*v.x; acc.y += w[c]*v.y;
            acc.z += w[c]*v.z; acc.w += w[c]*v.w;
        }
    }
    acc.x *= inv; acc.y *= inv; acc.z *= inv; acc.w *= inv;
    *reinterpret_cast<float4*>(&out[((size_t)b*T_ + qt*64 + r)*H_ + cb]) = acc;
}

extern "C" void kernel_launch(void* const* d_in, const int* in_sizes, int n_in,
                              void* d_out, int out_size)
{
    const float* x  = (const float*)d_in[0];
    const float* Wq = (const float*)d_in[1];
    const float* Wk = (const float*)d_in[2];
    const float* Wv = (const float*)d_in[3];
    float* out = (float*)d_out;

    cudaFuncSetAttribute(proj_gemm_kernel,
                         cudaFuncAttributeMaxDynamicSharedMemorySize, SM_TOT);
    cudaFuncSetAttribute(attn_part_kernel,
                         cudaFuncAttributeMaxDynamicSharedMemorySize, ASM_TOT);

    prep_B_kernel<<<(192 * 1024) / 256, 256>>>(Wq, Wk, Wv);
    proj_gemm_kernel<<<(B_ * T_) / 128, 512, SM_TOT>>>(x);
    attn_part_kernel<<<dim3(80, B_), 128, ASM_TOT>>>(out);
    attn_merge_kernel<<<dim3(24, B_, 4), 256>>>(out);
}

// round 11
// speedup vs baseline: 1.1895x; 1.0406x over previous
#include <cuda_runtime.h>
#include <cuda_bf16.h>
#include <cuda_fp16.h>
#include <math.h>
#include <stdint.h>

#define B_ 8
#define T_ 2048
#define C_ 1024
#define H_ 64
#define CHUNK 8          // KV tiles per attention CTA

// Q/K post-RoPE, fp16 hi/lo, row-major [B*T][64]
__device__ __align__(16) __half g_Qhi[B_*T_*H_];
__device__ __align__(16) __half g_Qlo[B_*T_*H_];
__device__ __align__(16) __half g_Khi[B_*T_*H_];
__device__ __align__(16) __half g_Klo[B_*T_*H_];
// V transposed [B][64 h][T], fp16 (single precision level — PV is 1-pass)
__device__ __align__(16) __half g_VThi[B_*H_*T_];
// W split bf16 hi/lo, K-major [192][1024]  (proj GEMM stays bf16 3-pass)
__device__ __align__(16) __nv_bfloat16 g_Bhi[192*1024];
__device__ __align__(16) __nv_bfloat16 g_Blo[192*1024];
// split-KV partials (qt >= 8 only): part = (b*32 + qt)*4 + chunk
__device__ __align__(16) float g_Opart[B_*32*4*64*64];
__device__ float g_mpart[B_*32*4*64];
__device__ float g_lpart[B_*32*4*64];

__device__ __forceinline__ uint32_t smem_u32(const void* p) {
    uint32_t a;
    asm("{ .reg .u64 t; cvta.to.shared.u64 t, %1; cvt.u32.u64 %0, t; }" : "=r"(a) : "l"(p));
    return a;
}
__device__ __forceinline__ void ldmx4(uint32_t& r0, uint32_t& r1, uint32_t& r2, uint32_t& r3,
                                      uint32_t addr) {
    asm volatile("ldmatrix.sync.aligned.m8n8.x4.shared.b16 {%0,%1,%2,%3}, [%4];"
                 : "=r"(r0), "=r"(r1), "=r"(r2), "=r"(r3) : "r"(addr));
}
// bf16 MMA (proj)
__device__ __forceinline__ void mma_bf16(float* c,
                                         uint32_t a0, uint32_t a1, uint32_t a2, uint32_t a3,
                                         uint32_t b0, uint32_t b1) {
    asm volatile("mma.sync.aligned.m16n8k16.row.col.f32.bf16.bf16.f32 "
                 "{%0,%1,%2,%3}, {%4,%5,%6,%7}, {%8,%9}, {%0,%1,%2,%3};"
                 : "+f"(c[0]), "+f"(c[1]), "+f"(c[2]), "+f"(c[3])
                 : "r"(a0), "r"(a1), "r"(a2), "r"(a3), "r"(b0), "r"(b1));
}
// fp16 MMA (attention)
__device__ __forceinline__ void mma_f16(float* c,
                                        uint32_t a0, uint32_t a1, uint32_t a2, uint32_t a3,
                                        uint32_t b0, uint32_t b1) {
    asm volatile("mma.sync.aligned.m16n8k16.row.col.f32.f16.f16.f32 "
                 "{%0,%1,%2,%3}, {%4,%5,%6,%7}, {%8,%9}, {%0,%1,%2,%3};"
                 : "+f"(c[0]), "+f"(c[1]), "+f"(c[2]), "+f"(c[3])
                 : "r"(a0), "r"(a1), "r"(a2), "r"(a3), "r"(b0), "r"(b1));
}
__device__ __forceinline__ uint32_t bf16x2(float a, float b) {
    __nv_bfloat16 h0 = __float2bfloat16(a), h1 = __float2bfloat16(b);
    return (uint32_t)__bfloat16_as_ushort(h0) | ((uint32_t)__bfloat16_as_ushort(h1) << 16);
}
__device__ __forceinline__ float bf16lo_res(float v) {
    return v - __bfloat162float(__float2bfloat16(v));
}
__device__ __forceinline__ uint32_t h2pack(float a, float b) {
    __half2 h = __floats2half2_rn(a, b);
    return *reinterpret_cast<uint32_t*>(&h);
}
__device__ __forceinline__ float h_lo_res(float v) {
    return v - __half2float(__float2half_rn(v));
}
#define CP_A16(dst, src) \
    asm volatile("cp.async.cg.shared.global [%0], [%1], 16;" :: "r"(dst), "l"(src))
#define CP_COMMIT() asm volatile("cp.async.commit_group;" ::: "memory")
#define CP_WAIT0()  asm volatile("cp.async.wait_group 0;" ::: "memory")

// ---------------------------------------------------------------------------
// Prep: split W{q,k,v} into bf16 hi/lo, K-major [192][1024]
// ---------------------------------------------------------------------------
__global__ __launch_bounds__(256) void prep_B_kernel(
    const float* __restrict__ Wq, const float* __restrict__ Wk, const float* __restrict__ Wv)
{
    int idx = blockIdx.x * 256 + threadIdx.x;
    int n = idx >> 10, k = idx & 1023;
    const float* W = (n < 64) ? Wq : (n < 128) ? Wk : Wv;
    float v = W[k * 64 + (n & 63)];
    __nv_bfloat16 h = __float2bfloat16(v);
    g_Bhi[idx] = h;
    g_Blo[idx] = __float2bfloat16(v - __bfloat162float(h));
}

// ---------------------------------------------------------------------------
// Projection GEMM (HMMA bf16 hi/lo split). M=128 x N=192 per CTA, 16 warps.
// Epilogue: RoPE, then write Q/K fp16 hi/lo row-major; V fp16 transposed.
// ---------------------------------------------------------------------------
#define PA_STR 72
#define SM_AHI 0
#define SM_ALO (128*PA_STR*2)
#define SM_BHI (2*128*PA_STR*2)
#define SM_BLO (SM_BHI + 192*PA_STR*2)
#define SM_TOT (SM_BLO + 192*PA_STR*2)

__global__ __launch_bounds__(512) void proj_gemm_kernel(const float* __restrict__ x)
{
    extern __shared__ char smem[];
    const uint32_t sbase = smem_u32(smem);
    const int tid    = threadIdx.x;
    const int wid    = tid >> 5;
    const int lane   = tid & 31;
    const int warp_m = wid >> 2;
    const int warp_n = wid & 3;
    const int m0     = blockIdx.x * 128;

    uint32_t aOff[2], bOff[3];
    {
        int mlo = (lane >> 3) & 1, khi = (lane >> 4) & 1, r8 = lane & 7;
        #pragma unroll
        for (int mt = 0; mt < 2; mt++)
            aOff[mt] = (uint32_t)((warp_m*32 + mt*16 + mlo*8 + r8) * (PA_STR*2) + khi*16);
        #pragma unroll
        for (int p = 0; p < 3; p++)
            bOff[p] = (uint32_t)((warp_n*48 + p*16 + khi*8 + r8) * (PA_STR*2) + mlo*16);
    }

    float acc[2][6][4];
    #pragma unroll
    for (int mt = 0; mt < 2; mt++)
        #pragma unroll
        for (int nt = 0; nt < 6; nt++)
            #pragma unroll
            for (int q = 0; q < 4; q++) acc[mt][nt][q] = 0.f;

    #pragma unroll 1
    for (int c = 0; c < 16; c++) {
        const int kc = c * 64;
        if (c > 0) __syncthreads();

        #pragma unroll
        for (int it = tid; it < 2048; it += 512) {
            int r = it >> 4, q = it & 15;
            float4 f = *reinterpret_cast<const float4*>(x + (size_t)(m0 + r) * C_ + kc + q*4);
            uint32_t h0 = bf16x2(f.x, f.y), h1 = bf16x2(f.z, f.w);
            uint32_t l0 = bf16x2(bf16lo_res(f.x), bf16lo_res(f.y));
            uint32_t l1 = bf16x2(bf16lo_res(f.z), bf16lo_res(f.w));
            uint32_t off = (uint32_t)(r * (PA_STR*2) + q * 8);
            *reinterpret_cast<uint2*>(smem + SM_AHI + off) = make_uint2(h0, h1);
            *reinterpret_cast<uint2*>(smem + SM_ALO + off) = make_uint2(l0, l1);
        }
        #pragma unroll
        for (int it = tid; it < 1536; it += 512) {
            int n = it >> 3, s = it & 7;
            uint32_t off = (uint32_t)(n * (PA_STR*2) + s * 16);
            *reinterpret_cast<uint4*>(smem + SM_BHI + off) =
                *reinterpret_cast<const uint4*>(g_Bhi + (size_t)n * 1024 + kc + s*8);
            *reinterpret_cast<uint4*>(smem + SM_BLO + off) =
                *reinterpret_cast<const uint4*>(g_Blo + (size_t)n * 1024 + kc + s*8);
        }
        __syncthreads();

        #pragma unroll 1
        for (int pass = 0; pass < 3; pass++) {
            uint32_t aBase = sbase + ((pass < 2) ? SM_AHI : SM_ALO);
            uint32_t bBase = sbase + ((pass == 1) ? SM_BLO : SM_BHI);
            #pragma unroll
            for (int ks = 0; ks < 4; ks++) {
                uint32_t kb = (uint32_t)(ks * 32);
                uint32_t a[2][4];
                #pragma unroll
                for (int mt = 0; mt < 2; mt++)
                    ldmx4(a[mt][0], a[mt][1], a[mt][2], a[mt][3], aBase + aOff[mt] + kb);
                uint32_t b[6][2];
                #pragma unroll
                for (int p = 0; p < 3; p++) {
                    uint32_t r0, r1, r2, r3;
                    ldmx4(r0, r1, r2, r3, bBase + bOff[p] + kb);
                    b[p*2][0] = r0; b[p*2][1] = r1;
                    b[p*2+1][0] = r2; b[p*2+1][1] = r3;
                }
                #pragma unroll
                for (int mt = 0; mt < 2; mt++)
                    #pragma unroll
                    for (int nt = 0; nt < 6; nt++)
                        mma_bf16(acc[mt][nt], a[mt][0], a[mt][1], a[mt][2], a[mt][3],
                                 b[nt][0], b[nt][1]);
            }
        }
    }

    const int g  = lane >> 2;
    const int tq = lane & 3;
    #pragma unroll
    for (int mt = 0; mt < 2; mt++) {
        int row0 = m0 + warp_m*32 + mt*16 + g;
        int rows[2] = { row0, row0 + 8 };
        #pragma unroll
        for (int nt = 0; nt < 6; nt++) {
            int col = warp_n*48 + nt*8 + 2*tq;
            int mat = col >> 6;
            int col_in = col & 63;
            if (mat < 2) {
                __half* dhi = (mat == 0) ? g_Qhi : g_Khi;
                __half* dlo = (mat == 0) ? g_Qlo : g_Klo;
                int pi = col_in >> 1;
                float inv = powf(10000.f, -(float)pi * (1.f / 32.f));
                #pragma unroll
                for (int rg = 0; rg < 2; rg++) {
                    int t = rows[rg] & (T_ - 1);
                    float sn, cs;
                    sincosf((float)t * inv, &sn, &cs);
                    float a0 = acc[mt][nt][rg*2], a1 = acc[mt][nt][rg*2 + 1];
                    float v0 = a0*cs - a1*sn, v1 = a1*cs + a0*sn;
                    size_t base = (size_t)rows[rg] * H_ + col_in;
                    *reinterpret_cast<uint32_t*>(&dhi[base]) = h2pack(v0, v1);
                    *reinterpret_cast<uint32_t*>(&dlo[base]) = h2pack(h_lo_res(v0), h_lo_res(v1));
                }
            } else {
                #pragma unroll
                for (int rg = 0; rg < 2; rg++) {
                    int bb = rows[rg] >> 11, tt = rows[rg] & (T_ - 1);
                    #pragma unroll
                    for (int e = 0; e < 2; e++) {
                        float v = acc[mt][nt][rg*2 + e];
                        size_t idx = ((size_t)bb * H_ + (col_in + e)) * T_ + tt;
                        g_VThi[idx] = __float2half_rn(v);
                    }
                }
            }
        }
    }
}

// ---------------------------------------------------------------------------
// Split-KV attention partial (fp16 split): S = Qh*Kh + Qh*Kl + Ql*Kh (3 passes);
// PV = Ph*Vh SINGLE pass (V fp16; Ph fp16). Register-lean, LB(128,4).
// smem: Q hi/lo + K hi/lo + V = 5 tiles = 46 KB -> 4 CTAs/SM.
// qt<8 writes output directly; qt>=8 emits partials for merge.
// ---------------------------------------------------------------------------
#define ASTR   72
#define TILE_B (64*ASTR*2)
#define AQHI   0
#define AQLO   TILE_B
#define AKV    (2*TILE_B)           // KHI, KLO, VHI
#define ASM_TOT (5*TILE_B)          // 46080

__device__ __forceinline__ void stage_kv(uint32_t sdst, int b, int kt, int tid) {
    const __half* Kh = g_Khi + ((size_t)b * T_ + kt*64) * H_;
    const __half* Kl = g_Klo + ((size_t)b * T_ + kt*64) * H_;
    #pragma unroll
    for (int it = tid; it < 512; it += 128) {
        int r = it >> 3, s = it & 7;
        uint32_t off = (uint32_t)(r * (ASTR*2) + s*16);
        CP_A16(sdst + off,            Kh + r*64 + s*8);
        CP_A16(sdst + TILE_B + off,   Kl + r*64 + s*8);
        size_t vsrc = ((size_t)b * H_ + r) * T_ + kt*64 + s*8;
        CP_A16(sdst + 2*TILE_B + off, g_VThi + vsrc);
    }
}

__global__ __launch_bounds__(128, 4) void attn_part_kernel(float* __restrict__ out)
{
    extern __shared__ char smem[];
    const uint32_t sbase = smem_u32(smem);
    const int tid  = threadIdx.x;
    const int wid  = tid >> 5;
    const int lane = tid & 31;
    const int b    = blockIdx.y;
    const int r8   = lane & 7;
    const int mlo  = (lane >> 3) & 1;
    const int khi  = (lane >> 4) & 1;
    const int g    = lane >> 2;
    const int tq   = lane & 3;
    const float scale = 0.125f;

    int qt = 0, chunk = 0;
    {
        int bx = blockIdx.x, acc = 0;
        #pragma unroll 1
        for (int q = 0; q < 32; q++) {
            int nc = (q >> 3) + 1;
            if (bx < acc + nc) { qt = q; chunk = bx - acc; break; }
            acc += nc;
        }
    }
    const int kt0 = chunk * CHUNK;
    const int kt1 = (kt0 + CHUNK - 1 < qt) ? (kt0 + CHUNK - 1) : qt;

    const uint32_t aRowOff = (uint32_t)((wid*16 + mlo*8 + r8) * (ASTR*2) + khi*16);
    uint32_t bRowOff[4];
    #pragma unroll
    for (int p = 0; p < 4; p++)
        bRowOff[p] = (uint32_t)((p*16 + khi*8 + r8) * (ASTR*2) + mlo*16);

    {
        const __half* Qh = g_Qhi + ((size_t)b * T_ + qt*64) * H_;
        const __half* Ql = g_Qlo + ((size_t)b * T_ + qt*64) * H_;
        #pragma unroll
        for (int it = tid; it < 512; it += 128) {
            int r = it >> 3, s = it & 7;
            uint32_t off = (uint32_t)(r * (ASTR*2) + s*16);
            CP_A16(sbase + AQHI + off, Qh + r*64 + s*8);
            CP_A16(sbase + AQLO + off, Ql + r*64 + s*8);
        }
        stage_kv(sbase + AKV, b, kt0, tid);
        CP_COMMIT();
    }
    CP_WAIT0();
    __syncthreads();

    float m0r = -1e30f, m1r = -1e30f, l0 = 0.f, l1 = 0.f;
    float o[8][4];
    #pragma unroll
    for (int nt = 0; nt < 8; nt++)
        #pragma unroll
        for (int q = 0; q < 4; q++) o[nt][q] = 0.f;

    #pragma unroll 1
    for (int kt = kt0; kt <= kt1; kt++) {
        const uint32_t kvb = sbase + AKV;

        float s_[8][4];
        #pragma unroll
        for (int nt = 0; nt < 8; nt++)
            #pragma unroll
            for (int q = 0; q < 4; q++) s_[nt][q] = 0.f;

        #pragma unroll
        for (int ks = 0; ks < 4; ks++) {
            uint32_t kb = (uint32_t)(ks * 32);
            uint32_t qh0, qh1, qh2, qh3, ql0, ql1, ql2, ql3;
            ldmx4(qh0, qh1, qh2, qh3, sbase + AQHI + aRowOff + kb);
            ldmx4(ql0, ql1, ql2, ql3, sbase + AQLO + aRowOff + kb);
            #pragma unroll
            for (int p = 0; p < 4; p++) {
                uint32_t kh0, kh1, kh2, kh3, kl0, kl1, kl2, kl3;
                ldmx4(kh0, kh1, kh2, kh3, kvb + bRowOff[p] + kb);
                ldmx4(kl0, kl1, kl2, kl3, kvb + TILE_B + bRowOff[p] + kb);
                mma_f16(s_[2*p],   qh0, qh1, qh2, qh3, kh0, kh1);
                mma_f16(s_[2*p+1], qh0, qh1, qh2, qh3, kh2, kh3);
                mma_f16(s_[2*p],   qh0, qh1, qh2, qh3, kl0, kl1);
                mma_f16(s_[2*p+1], qh0, qh1, qh2, qh3, kl2, kl3);
                mma_f16(s_[2*p],   ql0, ql1, ql2, ql3, kh0, kh1);
                mma_f16(s_[2*p+1], ql0, ql1, ql2, ql3, kh2, kh3);
            }
        }

        #pragma unroll
        for (int nt = 0; nt < 8; nt++)
            #pragma unroll
            for (int q = 0; q < 4; q++) s_[nt][q] *= scale;
        if (kt == qt) {
            int qr0 = qt*64 + wid*16 + g;
            #pragma unroll
            for (int nt = 0; nt < 8; nt++) {
                int kc0 = kt*64 + nt*8 + 2*tq;
                if (kc0     > qr0)     s_[nt][0] = -1e30f;
                if (kc0 + 1 > qr0)     s_[nt][1] = -1e30f;
                if (kc0     > qr0 + 8) s_[nt][2] = -1e30f;
                if (kc0 + 1 > qr0 + 8) s_[nt][3] = -1e30f;
            }
        }

        float mx0 = -1e30f, mx1 = -1e30f;
        #pragma unroll
        for (int nt = 0; nt < 8; nt++) {
            mx0 = fmaxf(mx0, fmaxf(s_[nt][0], s_[nt][1]));
            mx1 = fmaxf(mx1, fmaxf(s_[nt][2], s_[nt][3]));
        }
        mx0 = fmaxf(mx0, __shfl_xor_sync(0xffffffffu, mx0, 1));
        mx0 = fmaxf(mx0, __shfl_xor_sync(0xffffffffu, mx0, 2));
        mx1 = fmaxf(mx1, __shfl_xor_sync(0xffffffffu, mx1, 1));
        mx1 = fmaxf(mx1, __shfl_xor_sync(0xffffffffu, mx1, 2));
        float mn0 = fmaxf(m0r, mx0), mn1 = fmaxf(m1r, mx1);
        float al0 = __expf(m0r - mn0), al1 = __expf(m1r - mn1);
        float rs0 = 0.f, rs1 = 0.f;
        #pragma unroll
        for (int nt = 0; nt < 8; nt++) {
            s_[nt][0] = __expf(s_[nt][0] - mn0);
            s_[nt][1] = __expf(s_[nt][1] - mn0);
            s_[nt][2] = __expf(s_[nt][2] - mn1);
            s_[nt][3] = __expf(s_[nt][3] - mn1);
            rs0 += s_[nt][0] + s_[nt][1];
            rs1 += s_[nt][2] + s_[nt][3];
        }
        rs0 += __shfl_xor_sync(0xffffffffu, rs0, 1);
        rs0 += __shfl_xor_sync(0xffffffffu, rs0, 2);
        rs1 += __shfl_xor_sync(0xffffffffu, rs1, 1);
        rs1 += __shfl_xor_sync(0xffffffffu, rs1, 2);
        l0 = l0 * al0 + rs0;  l1 = l1 * al1 + rs1;
        m0r = mn0;  m1r = mn1;
        #pragma unroll
        for (int nt = 0; nt < 8; nt++) {
            o[nt][0] *= al0; o[nt][1] *= al0;
            o[nt][2] *= al1; o[nt][3] *= al1;
        }

        // ---- O += P V  (single pass: Ph * Vh) ----
        #pragma unroll
        for (int kk = 0; kk < 4; kk++) {
            uint32_t ah[4];
            ah[0] = h2pack(s_[2*kk][0],   s_[2*kk][1]);
            ah[1] = h2pack(s_[2*kk][2],   s_[2*kk][3]);
            ah[2] = h2pack(s_[2*kk+1][0], s_[2*kk+1][1]);
            ah[3] = h2pack(s_[2*kk+1][2], s_[2*kk+1][3]);
            uint32_t kb = (uint32_t)(kk * 32);
            #pragma unroll
            for (int p = 0; p < 4; p++) {
                uint32_t vh0, vh1, vh2, vh3;
                ldmx4(vh0, vh1, vh2, vh3, kvb + 2*TILE_B + bRowOff[p] + kb);
                mma_f16(o[2*p],   ah[0], ah[1], ah[2], ah[3], vh0, vh1);
                mma_f16(o[2*p+1], ah[0], ah[1], ah[2], ah[3], vh2, vh3);
            }
        }

        __syncthreads();
        if (kt < kt1) {
            stage_kv(sbase + AKV, b, kt + 1, tid);
            CP_COMMIT();
            CP_WAIT0();
            __syncthreads();
        }
    }

    const int row0 = wid*16 + g;
    if (qt < 8) {
        float rc0 = 1.f / l0, rc1 = 1.f / l1;
        #pragma unroll
        for (int nt = 0; nt < 8; nt++) {
            int col = nt*8 + 2*tq;
            *reinterpret_cast<float2*>(&out[((size_t)b*T_ + qt*64 + row0) * H_ + col]) =
                make_float2(o[nt][0]*rc0, o[nt][1]*rc0);
            *reinterpret_cast<float2*>(&out[((size_t)b*T_ + qt*64 + row0 + 8) * H_ + col]) =
                make_float2(o[nt][2]*rc1, o[nt][3]*rc1);
        }
    } else {
        const int part = (b*32 + qt)*4 + chunk;
        float* Op = g_Opart + (size_t)part * 64 * 64;
        #pragma unroll
        for (int nt = 0; nt < 8; nt++) {
            int col = nt*8 + 2*tq;
            *reinterpret_cast<float2*>(&Op[(row0)     * 64 + col]) = make_float2(o[nt][0], o[nt][1]);
            *reinterpret_cast<float2*>(&Op[(row0 + 8) * 64 + col]) = make_float2(o[nt][2], o[nt][3]);
        }
        if (tq == 0) {
            g_mpart[part*64 + row0]     = m0r;
            g_mpart[part*64 + row0 + 8] = m1r;
            g_lpart[part*64 + row0]     = l0;
            g_lpart[part*64 + row0 + 8] = l1;
        }
    }
}

// ---------------------------------------------------------------------------
// Merge: combine chunk partials per (b, qt) for qt >= 8; fine-grained grid.
// ---------------------------------------------------------------------------
__global__ __launch_bounds__(256) void attn_merge_kernel(float* __restrict__ out)
{
    const int qt = blockIdx.x + 8, b = blockIdx.y;
    const int nc = (qt >> 3) + 1;
    const int r  = (int)blockIdx.z * 16 + (threadIdx.x >> 4);  // 0..63
    const int cb = (threadIdx.x & 15) * 4;
    const int pbase = (b*32 + qt)*4;

    float m = -1e30f;
    #pragma unroll
    for (int c = 0; c < 4; c++)
        if (c < nc) m = fmaxf(m, g_mpart[(pbase + c)*64 + r]);
    float w[4];
    float l = 0.f;
    #pragma unroll
    for (int c = 0; c < 4; c++) {
        if (c < nc) {
            w[c] = __expf(g_mpart[(pbase + c)*64 + r] - m);
            l += w[c] * g_lpart[(pbase + c)*64 + r];
        } else w[c] = 0.f;
    }
    float inv = 1.f / l;

    float4 acc = make_float4(0.f, 0.f, 0.f, 0.f);
    #pragma unroll
    for (int c = 0; c < 4; c++) {
        if (c < nc) {
            float4 v = *reinterpret_cast<const float4*>(
                &g_Opart[((size_t)(pbase + c)*64 + r)*64 + cb]);
            acc.x += w[c]*v.x; acc.y += w[c]*v.y;
            acc.z += w[c]*v.z; acc.w += w[c]*v.w;
        }
    }
    acc.x *= inv; acc.y *= inv; acc.z *= inv; acc.w *= inv;
    *reinterpret_cast<float4*>(&out[((size_t)b*T_ + qt*64 + r)*H_ + cb]) = acc;
}

extern "C" void kernel_launch(void* const* d_in, const int* in_sizes, int n_in,
                              void* d_out, int out_size)
{
    const float* x  = (const float*)d_in[0];
    const float* Wq = (const float*)d_in[1];
    const float* Wk = (const float*)d_in[2];
    const float* Wv = (const float*)d_in[3];
    float* out = (float*)d_out;

    cudaFuncSetAttribute(proj_gemm_kernel,
                         cudaFuncAttributeMaxDynamicSharedMemorySize, SM_TOT);
    cudaFuncSetAttribute(attn_part_kernel,
                         cudaFuncAttributeMaxDynamicSharedMemorySize, ASM_TOT);

    prep_B_kernel<<<(192 * 1024) / 256, 256>>>(Wq, Wk, Wv);
    proj_gemm_kernel<<<(B_ * T_) / 128, 512, SM_TOT>>>(x);
    attn_part_kernel<<<dim3(80, B_), 128, ASM_TOT>>>(out);
    attn_merge_kernel<<<dim3(24, B_, 4), 256>>>(out);
}

// round 12
// speedup vs baseline: 1.2676x; 1.0656x over previous
#include <cuda_runtime.h>
#include <cuda_bf16.h>
#include <cuda_fp16.h>
#include <math.h>
#include <stdint.h>

#define B_ 8
#define T_ 2048
#define C_ 1024
#define H_ 64
#define CHUNK 8          // KV tiles per attention CTA

// Q post-RoPE, fp16 hi/lo; K post-RoPE fp16 (single); row-major [B*T][64]
__device__ __align__(16) __half g_Qhi[B_*T_*H_];
__device__ __align__(16) __half g_Qlo[B_*T_*H_];
__device__ __align__(16) __half g_Khi[B_*T_*H_];
// V transposed [B][64 h][T], fp16 (single — PV is 1-pass)
__device__ __align__(16) __half g_VThi[B_*H_*T_];
// W split bf16 hi/lo, K-major [192][1024]  (proj GEMM stays bf16 3-pass)
__device__ __align__(16) __nv_bfloat16 g_Bhi[192*1024];
__device__ __align__(16) __nv_bfloat16 g_Blo[192*1024];
// split-KV partials (qt >= 8 only): part = (b*32 + qt)*4 + chunk
__device__ __align__(16) float g_Opart[B_*32*4*64*64];
__device__ float g_mpart[B_*32*4*64];
__device__ float g_lpart[B_*32*4*64];

__device__ __forceinline__ uint32_t smem_u32(const void* p) {
    uint32_t a;
    asm("{ .reg .u64 t; cvta.to.shared.u64 t, %1; cvt.u32.u64 %0, t; }" : "=r"(a) : "l"(p));
    return a;
}
__device__ __forceinline__ void ldmx4(uint32_t& r0, uint32_t& r1, uint32_t& r2, uint32_t& r3,
                                      uint32_t addr) {
    asm volatile("ldmatrix.sync.aligned.m8n8.x4.shared.b16 {%0,%1,%2,%3}, [%4];"
                 : "=r"(r0), "=r"(r1), "=r"(r2), "=r"(r3) : "r"(addr));
}
// bf16 MMA (proj)
__device__ __forceinline__ void mma_bf16(float* c,
                                         uint32_t a0, uint32_t a1, uint32_t a2, uint32_t a3,
                                         uint32_t b0, uint32_t b1) {
    asm volatile("mma.sync.aligned.m16n8k16.row.col.f32.bf16.bf16.f32 "
                 "{%0,%1,%2,%3}, {%4,%5,%6,%7}, {%8,%9}, {%0,%1,%2,%3};"
                 : "+f"(c[0]), "+f"(c[1]), "+f"(c[2]), "+f"(c[3])
                 : "r"(a0), "r"(a1), "r"(a2), "r"(a3), "r"(b0), "r"(b1));
}
// fp16 MMA (attention)
__device__ __forceinline__ void mma_f16(float* c,
                                        uint32_t a0, uint32_t a1, uint32_t a2, uint32_t a3,
                                        uint32_t b0, uint32_t b1) {
    asm volatile("mma.sync.aligned.m16n8k16.row.col.f32.f16.f16.f32 "
                 "{%0,%1,%2,%3}, {%4,%5,%6,%7}, {%8,%9}, {%0,%1,%2,%3};"
                 : "+f"(c[0]), "+f"(c[1]), "+f"(c[2]), "+f"(c[3])
                 : "r"(a0), "r"(a1), "r"(a2), "r"(a3), "r"(b0), "r"(b1));
}
__device__ __forceinline__ uint32_t bf16x2(float a, float b) {
    __nv_bfloat16 h0 = __float2bfloat16(a), h1 = __float2bfloat16(b);
    return (uint32_t)__bfloat16_as_ushort(h0) | ((uint32_t)__bfloat16_as_ushort(h1) << 16);
}
__device__ __forceinline__ float bf16lo_res(float v) {
    return v - __bfloat162float(__float2bfloat16(v));
}
__device__ __forceinline__ uint32_t h2pack(float a, float b) {
    __half2 h = __floats2half2_rn(a, b);
    return *reinterpret_cast<uint32_t*>(&h);
}
__device__ __forceinline__ float h_lo_res(float v) {
    return v - __half2float(__float2half_rn(v));
}
#define CP_A16(dst, src) \
    asm volatile("cp.async.cg.shared.global [%0], [%1], 16;" :: "r"(dst), "l"(src))
#define CP_COMMIT() asm volatile("cp.async.commit_group;" ::: "memory")
#define CP_WAIT0()  asm volatile("cp.async.wait_group 0;" ::: "memory")

// ---------------------------------------------------------------------------
// Prep: split W{q,k,v} into bf16 hi/lo, K-major [192][1024]
// ---------------------------------------------------------------------------
__global__ __launch_bounds__(256) void prep_B_kernel(
    const float* __restrict__ Wq, const float* __restrict__ Wk, const float* __restrict__ Wv)
{
    int idx = blockIdx.x * 256 + threadIdx.x;
    int n = idx >> 10, k = idx & 1023;
    const float* W = (n < 64) ? Wq : (n < 128) ? Wk : Wv;
    float v = W[k * 64 + (n & 63)];
    __nv_bfloat16 h = __float2bfloat16(v);
    g_Bhi[idx] = h;
    g_Blo[idx] = __float2bfloat16(v - __bfloat162float(h));
}

// ---------------------------------------------------------------------------
// Projection GEMM (HMMA bf16 hi/lo split). M=128 x N=192 per CTA, 16 warps.
// Epilogue: RoPE, then write Q fp16 hi/lo; K fp16; V fp16 transposed.
// ---------------------------------------------------------------------------
#define PA_STR 72
#define SM_AHI 0
#define SM_ALO (128*PA_STR*2)
#define SM_BHI (2*128*PA_STR*2)
#define SM_BLO (SM_BHI + 192*PA_STR*2)
#define SM_TOT (SM_BLO + 192*PA_STR*2)

__global__ __launch_bounds__(512) void proj_gemm_kernel(const float* __restrict__ x)
{
    extern __shared__ char smem[];
    const uint32_t sbase = smem_u32(smem);
    const int tid    = threadIdx.x;
    const int wid    = tid >> 5;
    const int lane   = tid & 31;
    const int warp_m = wid >> 2;
    const int warp_n = wid & 3;
    const int m0     = blockIdx.x * 128;

    uint32_t aOff[2], bOff[3];
    {
        int mlo = (lane >> 3) & 1, khi = (lane >> 4) & 1, r8 = lane & 7;
        #pragma unroll
        for (int mt = 0; mt < 2; mt++)
            aOff[mt] = (uint32_t)((warp_m*32 + mt*16 + mlo*8 + r8) * (PA_STR*2) + khi*16);
        #pragma unroll
        for (int p = 0; p < 3; p++)
            bOff[p] = (uint32_t)((warp_n*48 + p*16 + khi*8 + r8) * (PA_STR*2) + mlo*16);
    }

    float acc[2][6][4];
    #pragma unroll
    for (int mt = 0; mt < 2; mt++)
        #pragma unroll
        for (int nt = 0; nt < 6; nt++)
            #pragma unroll
            for (int q = 0; q < 4; q++) acc[mt][nt][q] = 0.f;

    #pragma unroll 1
    for (int c = 0; c < 16; c++) {
        const int kc = c * 64;
        if (c > 0) __syncthreads();

        #pragma unroll
        for (int it = tid; it < 2048; it += 512) {
            int r = it >> 4, q = it & 15;
            float4 f = *reinterpret_cast<const float4*>(x + (size_t)(m0 + r) * C_ + kc + q*4);
            uint32_t h0 = bf16x2(f.x, f.y), h1 = bf16x2(f.z, f.w);
            uint32_t l0 = bf16x2(bf16lo_res(f.x), bf16lo_res(f.y));
            uint32_t l1 = bf16x2(bf16lo_res(f.z), bf16lo_res(f.w));
            uint32_t off = (uint32_t)(r * (PA_STR*2) + q * 8);
            *reinterpret_cast<uint2*>(smem + SM_AHI + off) = make_uint2(h0, h1);
            *reinterpret_cast<uint2*>(smem + SM_ALO + off) = make_uint2(l0, l1);
        }
        #pragma unroll
        for (int it = tid; it < 1536; it += 512) {
            int n = it >> 3, s = it & 7;
            uint32_t off = (uint32_t)(n * (PA_STR*2) + s * 16);
            *reinterpret_cast<uint4*>(smem + SM_BHI + off) =
                *reinterpret_cast<const uint4*>(g_Bhi + (size_t)n * 1024 + kc + s*8);
            *reinterpret_cast<uint4*>(smem + SM_BLO + off) =
                *reinterpret_cast<const uint4*>(g_Blo + (size_t)n * 1024 + kc + s*8);
        }
        __syncthreads();

        #pragma unroll 1
        for (int pass = 0; pass < 3; pass++) {
            uint32_t aBase = sbase + ((pass < 2) ? SM_AHI : SM_ALO);
            uint32_t bBase = sbase + ((pass == 1) ? SM_BLO : SM_BHI);
            #pragma unroll
            for (int ks = 0; ks < 4; ks++) {
                uint32_t kb = (uint32_t)(ks * 32);
                uint32_t a[2][4];
                #pragma unroll
                for (int mt = 0; mt < 2; mt++)
                    ldmx4(a[mt][0], a[mt][1], a[mt][2], a[mt][3], aBase + aOff[mt] + kb);
                uint32_t b[6][2];
                #pragma unroll
                for (int p = 0; p < 3; p++) {
                    uint32_t r0, r1, r2, r3;
                    ldmx4(r0, r1, r2, r3, bBase + bOff[p] + kb);
                    b[p*2][0] = r0; b[p*2][1] = r1;
                    b[p*2+1][0] = r2; b[p*2+1][1] = r3;
                }
                #pragma unroll
                for (int mt = 0; mt < 2; mt++)
                    #pragma unroll
                    for (int nt = 0; nt < 6; nt++)
                        mma_bf16(acc[mt][nt], a[mt][0], a[mt][1], a[mt][2], a[mt][3],
                                 b[nt][0], b[nt][1]);
            }
        }
    }

    const int g  = lane >> 2;
    const int tq = lane & 3;
    #pragma unroll
    for (int mt = 0; mt < 2; mt++) {
        int row0 = m0 + warp_m*32 + mt*16 + g;
        int rows[2] = { row0, row0 + 8 };
        #pragma unroll
        for (int nt = 0; nt < 6; nt++) {
            int col = warp_n*48 + nt*8 + 2*tq;
            int mat = col >> 6;
            int col_in = col & 63;
            if (mat < 2) {
                int pi = col_in >> 1;
                float inv = powf(10000.f, -(float)pi * (1.f / 32.f));
                #pragma unroll
                for (int rg = 0; rg < 2; rg++) {
                    int t = rows[rg] & (T_ - 1);
                    float sn, cs;
                    sincosf((float)t * inv, &sn, &cs);
                    float a0 = acc[mt][nt][rg*2], a1 = acc[mt][nt][rg*2 + 1];
                    float v0 = a0*cs - a1*sn, v1 = a1*cs + a0*sn;
                    size_t base = (size_t)rows[rg] * H_ + col_in;
                    if (mat == 0) {
                        *reinterpret_cast<uint32_t*>(&g_Qhi[base]) = h2pack(v0, v1);
                        *reinterpret_cast<uint32_t*>(&g_Qlo[base]) =
                            h2pack(h_lo_res(v0), h_lo_res(v1));
                    } else {
                        *reinterpret_cast<uint32_t*>(&g_Khi[base]) = h2pack(v0, v1);
                    }
                }
            } else {
                #pragma unroll
                for (int rg = 0; rg < 2; rg++) {
                    int bb = rows[rg] >> 11, tt = rows[rg] & (T_ - 1);
                    #pragma unroll
                    for (int e = 0; e < 2; e++) {
                        float v = acc[mt][nt][rg*2 + e];
                        size_t idx = ((size_t)bb * H_ + (col_in + e)) * T_ + tt;
                        g_VThi[idx] = __float2half_rn(v);
                    }
                }
            }
        }
    }
}

// ---------------------------------------------------------------------------
// Split-KV attention partial: S = Qh*Kh + Ql*Kh (2 passes; Q hi/lo, K fp16);
// PV = Ph*Vh single pass. Register-lean, LB(128,4).
// smem: Q hi/lo + K + V = 4 tiles = 36.9 KB -> 4 CTAs/SM.
// qt<8 writes output directly; qt>=8 emits partials for merge.
// ---------------------------------------------------------------------------
#define ASTR   72
#define TILE_B (64*ASTR*2)
#define AQHI   0
#define AQLO   TILE_B
#define AKV    (2*TILE_B)           // K, V
#define ASM_TOT (4*TILE_B)          // 36864

__device__ __forceinline__ void stage_kv(uint32_t sdst, int b, int kt, int tid) {
    const __half* Kh = g_Khi + ((size_t)b * T_ + kt*64) * H_;
    #pragma unroll
    for (int it = tid; it < 512; it += 128) {
        int r = it >> 3, s = it & 7;
        uint32_t off = (uint32_t)(r * (ASTR*2) + s*16);
        CP_A16(sdst + off, Kh + r*64 + s*8);
        size_t vsrc = ((size_t)b * H_ + r) * T_ + kt*64 + s*8;
        CP_A16(sdst + TILE_B + off, g_VThi + vsrc);
    }
}

__global__ __launch_bounds__(128, 4) void attn_part_kernel(float* __restrict__ out)
{
    extern __shared__ char smem[];
    const uint32_t sbase = smem_u32(smem);
    const int tid  = threadIdx.x;
    const int wid  = tid >> 5;
    const int lane = tid & 31;
    const int b    = blockIdx.y;
    const int r8   = lane & 7;
    const int mlo  = (lane >> 3) & 1;
    const int khi  = (lane >> 4) & 1;
    const int g    = lane >> 2;
    const int tq   = lane & 3;
    const float scale = 0.125f;

    int qt = 0, chunk = 0;
    {
        int bx = blockIdx.x, acc = 0;
        #pragma unroll 1
        for (int q = 0; q < 32; q++) {
            int nc = (q >> 3) + 1;
            if (bx < acc + nc) { qt = q; chunk = bx - acc; break; }
            acc += nc;
        }
    }
    const int kt0 = chunk * CHUNK;
    const int kt1 = (kt0 + CHUNK - 1 < qt) ? (kt0 + CHUNK - 1) : qt;

    const uint32_t aRowOff = (uint32_t)((wid*16 + mlo*8 + r8) * (ASTR*2) + khi*16);
    uint32_t bRowOff[4];
    #pragma unroll
    for (int p = 0; p < 4; p++)
        bRowOff[p] = (uint32_t)((p*16 + khi*8 + r8) * (ASTR*2) + mlo*16);

    {
        const __half* Qh = g_Qhi + ((size_t)b * T_ + qt*64) * H_;
        const __half* Ql = g_Qlo + ((size_t)b * T_ + qt*64) * H_;
        #pragma unroll
        for (int it = tid; it < 512; it += 128) {
            int r = it >> 3, s = it & 7;
            uint32_t off = (uint32_t)(r * (ASTR*2) + s*16);
            CP_A16(sbase + AQHI + off, Qh + r*64 + s*8);
            CP_A16(sbase + AQLO + off, Ql + r*64 + s*8);
        }
        stage_kv(sbase + AKV, b, kt0, tid);
        CP_COMMIT();
    }
    CP_WAIT0();
    __syncthreads();

    float m0r = -1e30f, m1r = -1e30f, l0 = 0.f, l1 = 0.f;
    float o[8][4];
    #pragma unroll
    for (int nt = 0; nt < 8; nt++)
        #pragma unroll
        for (int q = 0; q < 4; q++) o[nt][q] = 0.f;

    #pragma unroll 1
    for (int kt = kt0; kt <= kt1; kt++) {
        const uint32_t kvb = sbase + AKV;

        float s_[8][4];
        #pragma unroll
        for (int nt = 0; nt < 8; nt++)
            #pragma unroll
            for (int q = 0; q < 4; q++) s_[nt][q] = 0.f;

        #pragma unroll
        for (int ks = 0; ks < 4; ks++) {
            uint32_t kb = (uint32_t)(ks * 32);
            uint32_t qh0, qh1, qh2, qh3, ql0, ql1, ql2, ql3;
            ldmx4(qh0, qh1, qh2, qh3, sbase + AQHI + aRowOff + kb);
            ldmx4(ql0, ql1, ql2, ql3, sbase + AQLO + aRowOff + kb);
            #pragma unroll
            for (int p = 0; p < 4; p++) {
                uint32_t kh0, kh1, kh2, kh3;
                ldmx4(kh0, kh1, kh2, kh3, kvb + bRowOff[p] + kb);
                mma_f16(s_[2*p],   qh0, qh1, qh2, qh3, kh0, kh1);
                mma_f16(s_[2*p+1], qh0, qh1, qh2, qh3, kh2, kh3);
                mma_f16(s_[2*p],   ql0, ql1, ql2, ql3, kh0, kh1);
                mma_f16(s_[2*p+1], ql0, ql1, ql2, ql3, kh2, kh3);
            }
        }

        #pragma unroll
        for (int nt = 0; nt < 8; nt++)
            #pragma unroll
            for (int q = 0; q < 4; q++) s_[nt][q] *= scale;
        if (kt == qt) {
            int qr0 = qt*64 + wid*16 + g;
            #pragma unroll
            for (int nt = 0; nt < 8; nt++) {
                int kc0 = kt*64 + nt*8 + 2*tq;
                if (kc0     > qr0)     s_[nt][0] = -1e30f;
                if (kc0 + 1 > qr0)     s_[nt][1] = -1e30f;
                if (kc0     > qr0 + 8) s_[nt][2] = -1e30f;
                if (kc0 + 1 > qr0 + 8) s_[nt][3] = -1e30f;
            }
        }

        float mx0 = -1e30f, mx1 = -1e30f;
        #pragma unroll
        for (int nt = 0; nt < 8; nt++) {
            mx0 = fmaxf(mx0, fmaxf(s_[nt][0], s_[nt][1]));
            mx1 = fmaxf(mx1, fmaxf(s_[nt][2], s_[nt][3]));
        }
        mx0 = fmaxf(mx0, __shfl_xor_sync(0xffffffffu, mx0, 1));
        mx0 = fmaxf(mx0, __shfl_xor_sync(0xffffffffu, mx0, 2));
        mx1 = fmaxf(mx1, __shfl_xor_sync(0xffffffffu, mx1, 1));
        mx1 = fmaxf(mx1, __shfl_xor_sync(0xffffffffu, mx1, 2));
        float mn0 = fmaxf(m0r, mx0), mn1 = fmaxf(m1r, mx1);
        float al0 = __expf(m0r - mn0), al1 = __expf(m1r - mn1);
        float rs0 = 0.f, rs1 = 0.f;
        #pragma unroll
        for (int nt = 0; nt < 8; nt++) {
            s_[nt][0] = __expf(s_[nt][0] - mn0);
            s_[nt][1] = __expf(s_[nt][1] - mn0);
            s_[nt][2] = __expf(s_[nt][2] - mn1);
            s_[nt][3] = __expf(s_[nt][3] - mn1);
            rs0 += s_[nt][0] + s_[nt][1];
            rs1 += s_[nt][2] + s_[nt][3];
        }
        rs0 += __shfl_xor_sync(0xffffffffu, rs0, 1);
        rs0 += __shfl_xor_sync(0xffffffffu, rs0, 2);
        rs1 += __shfl_xor_sync(0xffffffffu, rs1, 1);
        rs1 += __shfl_xor_sync(0xffffffffu, rs1, 2);
        l0 = l0 * al0 + rs0;  l1 = l1 * al1 + rs1;
        m0r = mn0;  m1r = mn1;
        #pragma unroll
        for (int nt = 0; nt < 8; nt++) {
            o[nt][0] *= al0; o[nt][1] *= al0;
            o[nt][2] *= al1; o[nt][3] *= al1;
        }

        // ---- O += P V  (single pass: Ph * Vh) ----
        #pragma unroll
        for (int kk = 0; kk < 4; kk++) {
            uint32_t ah[4];
            ah[0] = h2pack(s_[2*kk][0],   s_[2*kk][1]);
            ah[1] = h2pack(s_[2*kk][2],   s_[2*kk][3]);
            ah[2] = h2pack(s_[2*kk+1][0], s_[2*kk+1][1]);
            ah[3] = h2pack(s_[2*kk+1][2], s_[2*kk+1][3]);
            uint32_t kb = (uint32_t)(kk * 32);
            #pragma unroll
            for (int p = 0; p < 4; p++) {
                uint32_t vh0, vh1, vh2, vh3;
                ldmx4(vh0, vh1, vh2, vh3, kvb + TILE_B + bRowOff[p] + kb);
                mma_f16(o[2*p],   ah[0], ah[1], ah[2], ah[3], vh0, vh1);
                mma_f16(o[2*p+1], ah[0], ah[1], ah[2], ah[3], vh2, vh3);
            }
        }

        __syncthreads();
        if (kt < kt1) {
            stage_kv(sbase + AKV, b, kt + 1, tid);
            CP_COMMIT();
            CP_WAIT0();
            __syncthreads();
        }
    }

    const int row0 = wid*16 + g;
    if (qt < 8) {
        float rc0 = 1.f / l0, rc1 = 1.f / l1;
        #pragma unroll
        for (int nt = 0; nt < 8; nt++) {
            int col = nt*8 + 2*tq;
            *reinterpret_cast<float2*>(&out[((size_t)b*T_ + qt*64 + row0) * H_ + col]) =
                make_float2(o[nt][0]*rc0, o[nt][1]*rc0);
            *reinterpret_cast<float2*>(&out[((size_t)b*T_ + qt*64 + row0 + 8) * H_ + col]) =
                make_float2(o[nt][2]*rc1, o[nt][3]*rc1);
        }
    } else {
        const int part = (b*32 + qt)*4 + chunk;
        float* Op = g_Opart + (size_t)part * 64 * 64;
        #pragma unroll
        for (int nt = 0; nt < 8; nt++) {
            int col = nt*8 + 2*tq;
            *reinterpret_cast<float2*>(&Op[(row0)     * 64 + col]) = make_float2(o[nt][0], o[nt][1]);
            *reinterpret_cast<float2*>(&Op[(row0 + 8) * 64 + col]) = make_float2(o[nt][2], o[nt][3]);
        }
        if (tq == 0) {
            g_mpart[part*64 + row0]     = m0r;
            g_mpart[part*64 + row0 + 8] = m1r;
            g_lpart[part*64 + row0]     = l0;
            g_lpart[part*64 + row0 + 8] = l1;
        }
    }
}

// ---------------------------------------------------------------------------
// Merge: combine chunk partials per (b, qt) for qt >= 8; fine-grained grid.
// ---------------------------------------------------------------------------
__global__ __launch_bounds__(256) void attn_merge_kernel(float* __restrict__ out)
{
    const int qt = blockIdx.x + 8, b = blockIdx.y;
    const int nc = (qt >> 3) + 1;
    const int r  = (int)blockIdx.z * 16 + (threadIdx.x >> 4);  // 0..63
    const int cb = (threadIdx.x & 15) * 4;
    const int pbase = (b*32 + qt)*4;

    float m = -1e30f;
    #pragma unroll
    for (int c = 0; c < 4; c++)
        if (c < nc) m = fmaxf(m, g_mpart[(pbase + c)*64 + r]);
    float w[4];
    float l = 0.f;
    #pragma unroll
    for (int c = 0; c < 4; c++) {
        if (c < nc) {
            w[c] = __expf(g_mpart[(pbase + c)*64 + r] - m);
            l += w[c] * g_lpart[(pbase + c)*64 + r];
        } else w[c] = 0.f;
    }
    float inv = 1.f / l;

    float4 acc = make_float4(0.f, 0.f, 0.f, 0.f);
    #pragma unroll
    for (int c = 0; c < 4; c++) {
        if (c < nc) {
            float4 v = *reinterpret_cast<const float4*>(
                &g_Opart[((size_t)(pbase + c)*64 + r)*64 + cb]);
            acc.x += w[c]*v.x; acc.y += w[c]*v.y;
            acc.z += w[c]*v.z; acc.w += w[c]*v.w;
        }
    }
    acc.x *= inv; acc.y *= inv; acc.z *= inv; acc.w *= inv;
    *reinterpret_cast<float4*>(&out[((size_t)b*T_ + qt*64 + r)*H_ + cb]) = acc;
}

extern "C" void kernel_launch(void* const* d_in, const int* in_sizes, int n_in,
                              void* d_out, int out_size)
{
    const float* x  = (const float*)d_in[0];
    const float* Wq = (const float*)d_in[1];
    const float* Wk = (const float*)d_in[2];
    const float* Wv = (const float*)d_in[3];
    float* out = (float*)d_out;

    cudaFuncSetAttribute(proj_gemm_kernel,
                         cudaFuncAttributeMaxDynamicSharedMemorySize, SM_TOT);
    cudaFuncSetAttribute(attn_part_kernel,
                         cudaFuncAttributeMaxDynamicSharedMemorySize, ASM_TOT);

    prep_B_kernel<<<(192 * 1024) / 256, 256>>>(Wq, Wk, Wv);
    proj_gemm_kernel<<<(B_ * T_) / 128, 512, SM_TOT>>>(x);
    attn_part_kernel<<<dim3(80, B_), 128, ASM_TOT>>>(out);
    attn_merge_kernel<<<dim3(24, B_, 4), 256>>>(out);
}

// round 13
// speedup vs baseline: 1.2770x; 1.0074x over previous
#include <cuda_runtime.h>
#include <cuda_bf16.h>
#include <cuda_fp16.h>
#include <math.h>
#include <stdint.h>

#define B_ 8
#define T_ 2048
#define C_ 1024
#define H_ 64
#define CHUNK 8          // KV tiles per attention CTA

// Q post-RoPE, fp16 hi/lo; K post-RoPE fp16 (single); row-major [B*T][64]
__device__ __align__(16) __half g_Qhi[B_*T_*H_];
__device__ __align__(16) __half g_Qlo[B_*T_*H_];
__device__ __align__(16) __half g_Khi[B_*T_*H_];
// V transposed [B][64 h][T], fp16 (single — PV is 1-pass)
__device__ __align__(16) __half g_VThi[B_*H_*T_];
// W split bf16 hi/lo, K-major [192][1024]  (proj GEMM stays bf16 3-pass)
__device__ __align__(16) __nv_bfloat16 g_Bhi[192*1024];
__device__ __align__(16) __nv_bfloat16 g_Blo[192*1024];
// split-KV partials (qt >= 8 only): part = (b*32 + qt)*4 + chunk
// NOTE: m is tracked in base-2 scaled space (s * scale * log2e)
__device__ __align__(16) float g_Opart[B_*32*4*64*64];
__device__ float g_mpart[B_*32*4*64];
__device__ float g_lpart[B_*32*4*64];

__device__ __forceinline__ uint32_t smem_u32(const void* p) {
    uint32_t a;
    asm("{ .reg .u64 t; cvta.to.shared.u64 t, %1; cvt.u32.u64 %0, t; }" : "=r"(a) : "l"(p));
    return a;
}
__device__ __forceinline__ void ldmx4(uint32_t& r0, uint32_t& r1, uint32_t& r2, uint32_t& r3,
                                      uint32_t addr) {
    asm volatile("ldmatrix.sync.aligned.m8n8.x4.shared.b16 {%0,%1,%2,%3}, [%4];"
                 : "=r"(r0), "=r"(r1), "=r"(r2), "=r"(r3) : "r"(addr));
}
// bf16 MMA (proj)
__device__ __forceinline__ void mma_bf16(float* c,
                                         uint32_t a0, uint32_t a1, uint32_t a2, uint32_t a3,
                                         uint32_t b0, uint32_t b1) {
    asm volatile("mma.sync.aligned.m16n8k16.row.col.f32.bf16.bf16.f32 "
                 "{%0,%1,%2,%3}, {%4,%5,%6,%7}, {%8,%9}, {%0,%1,%2,%3};"
                 : "+f"(c[0]), "+f"(c[1]), "+f"(c[2]), "+f"(c[3])
                 : "r"(a0), "r"(a1), "r"(a2), "r"(a3), "r"(b0), "r"(b1));
}
// fp16 MMA (attention)
__device__ __forceinline__ void mma_f16(float* c,
                                        uint32_t a0, uint32_t a1, uint32_t a2, uint32_t a3,
                                        uint32_t b0, uint32_t b1) {
    asm volatile("mma.sync.aligned.m16n8k16.row.col.f32.f16.f16.f32 "
                 "{%0,%1,%2,%3}, {%4,%5,%6,%7}, {%8,%9}, {%0,%1,%2,%3};"
                 : "+f"(c[0]), "+f"(c[1]), "+f"(c[2]), "+f"(c[3])
                 : "r"(a0), "r"(a1), "r"(a2), "r"(a3), "r"(b0), "r"(b1));
}
__device__ __forceinline__ uint32_t bf16x2(float a, float b) {
    __nv_bfloat16 h0 = __float2bfloat16(a), h1 = __float2bfloat16(b);
    return (uint32_t)__bfloat16_as_ushort(h0) | ((uint32_t)__bfloat16_as_ushort(h1) << 16);
}
__device__ __forceinline__ float bf16lo_res(float v) {
    return v - __bfloat162float(__float2bfloat16(v));
}
__device__ __forceinline__ uint32_t h2pack(float a, float b) {
    __half2 h = __floats2half2_rn(a, b);
    return *reinterpret_cast<uint32_t*>(&h);
}
__device__ __forceinline__ float h_lo_res(float v) {
    return v - __half2float(__float2half_rn(v));
}
__device__ __forceinline__ float ex2f(float x) {
    float r; asm("ex2.approx.f32 %0, %1;" : "=f"(r) : "f"(x)); return r;
}
__device__ __forceinline__ uint32_t ex2_h2(uint32_t x) {
    uint32_t r; asm("ex2.approx.f16x2 %0, %1;" : "=r"(r) : "r"(x)); return r;
}
__device__ __forceinline__ float2 h2f2(uint32_t x) {
    __half2 h = *reinterpret_cast<__half2*>(&x);
    return __half22float2(h);
}
#define CP_A16(dst, src) \
    asm volatile("cp.async.cg.shared.global [%0], [%1], 16;" :: "r"(dst), "l"(src))
#define CP_COMMIT() asm volatile("cp.async.commit_group;" ::: "memory")
#define CP_WAIT0()  asm volatile("cp.async.wait_group 0;" ::: "memory")
#define CP_WAIT1()  asm volatile("cp.async.wait_group 1;" ::: "memory")

// ---------------------------------------------------------------------------
// Prep: split W{q,k,v} into bf16 hi/lo, K-major [192][1024]
// ---------------------------------------------------------------------------
__global__ __launch_bounds__(256) void prep_B_kernel(
    const float* __restrict__ Wq, const float* __restrict__ Wk, const float* __restrict__ Wv)
{
    int idx = blockIdx.x * 256 + threadIdx.x;
    int n = idx >> 10, k = idx & 1023;
    const float* W = (n < 64) ? Wq : (n < 128) ? Wk : Wv;
    float v = W[k * 64 + (n & 63)];
    __nv_bfloat16 h = __float2bfloat16(v);
    g_Bhi[idx] = h;
    g_Blo[idx] = __float2bfloat16(v - __bfloat162float(h));
}

// ---------------------------------------------------------------------------
// Projection GEMM (HMMA bf16 hi/lo split). M=128 x N=192 per CTA, 16 warps.
// Epilogue: RoPE, then write Q fp16 hi/lo; K fp16; V fp16 transposed.
// ---------------------------------------------------------------------------
#define PA_STR 72
#define SM_AHI 0
#define SM_ALO (128*PA_STR*2)
#define SM_BHI (2*128*PA_STR*2)
#define SM_BLO (SM_BHI + 192*PA_STR*2)
#define SM_TOT (SM_BLO + 192*PA_STR*2)

__global__ __launch_bounds__(512) void proj_gemm_kernel(const float* __restrict__ x)
{
    extern __shared__ char smem[];
    const uint32_t sbase = smem_u32(smem);
    const int tid    = threadIdx.x;
    const int wid    = tid >> 5;
    const int lane   = tid & 31;
    const int warp_m = wid >> 2;
    const int warp_n = wid & 3;
    const int m0     = blockIdx.x * 128;

    uint32_t aOff[2], bOff[3];
    {
        int mlo = (lane >> 3) & 1, khi = (lane >> 4) & 1, r8 = lane & 7;
        #pragma unroll
        for (int mt = 0; mt < 2; mt++)
            aOff[mt] = (uint32_t)((warp_m*32 + mt*16 + mlo*8 + r8) * (PA_STR*2) + khi*16);
        #pragma unroll
        for (int p = 0; p < 3; p++)
            bOff[p] = (uint32_t)((warp_n*48 + p*16 + khi*8 + r8) * (PA_STR*2) + mlo*16);
    }

    float acc[2][6][4];
    #pragma unroll
    for (int mt = 0; mt < 2; mt++)
        #pragma unroll
        for (int nt = 0; nt < 6; nt++)
            #pragma unroll
            for (int q = 0; q < 4; q++) acc[mt][nt][q] = 0.f;

    #pragma unroll 1
    for (int c = 0; c < 16; c++) {
        const int kc = c * 64;
        if (c > 0) __syncthreads();

        #pragma unroll
        for (int it = tid; it < 2048; it += 512) {
            int r = it >> 4, q = it & 15;
            float4 f = *reinterpret_cast<const float4*>(x + (size_t)(m0 + r) * C_ + kc + q*4);
            uint32_t h0 = bf16x2(f.x, f.y), h1 = bf16x2(f.z, f.w);
            uint32_t l0 = bf16x2(bf16lo_res(f.x), bf16lo_res(f.y));
            uint32_t l1 = bf16x2(bf16lo_res(f.z), bf16lo_res(f.w));
            uint32_t off = (uint32_t)(r * (PA_STR*2) + q * 8);
            *reinterpret_cast<uint2*>(smem + SM_AHI + off) = make_uint2(h0, h1);
            *reinterpret_cast<uint2*>(smem + SM_ALO + off) = make_uint2(l0, l1);
        }
        #pragma unroll
        for (int it = tid; it < 1536; it += 512) {
            int n = it >> 3, s = it & 7;
            uint32_t off = (uint32_t)(n * (PA_STR*2) + s * 16);
            *reinterpret_cast<uint4*>(smem + SM_BHI + off) =
                *reinterpret_cast<const uint4*>(g_Bhi + (size_t)n * 1024 + kc + s*8);
            *reinterpret_cast<uint4*>(smem + SM_BLO + off) =
                *reinterpret_cast<const uint4*>(g_Blo + (size_t)n * 1024 + kc + s*8);
        }
        __syncthreads();

        #pragma unroll 1
        for (int pass = 0; pass < 3; pass++) {
            uint32_t aBase = sbase + ((pass < 2) ? SM_AHI : SM_ALO);
            uint32_t bBase = sbase + ((pass == 1) ? SM_BLO : SM_BHI);
            #pragma unroll
            for (int ks = 0; ks < 4; ks++) {
                uint32_t kb = (uint32_t)(ks * 32);
                uint32_t a[2][4];
                #pragma unroll
                for (int mt = 0; mt < 2; mt++)
                    ldmx4(a[mt][0], a[mt][1], a[mt][2], a[mt][3], aBase + aOff[mt] + kb);
                uint32_t b[6][2];
                #pragma unroll
                for (int p = 0; p < 3; p++) {
                    uint32_t r0, r1, r2, r3;
                    ldmx4(r0, r1, r2, r3, bBase + bOff[p] + kb);
                    b[p*2][0] = r0; b[p*2][1] = r1;
                    b[p*2+1][0] = r2; b[p*2+1][1] = r3;
                }
                #pragma unroll
                for (int mt = 0; mt < 2; mt++)
                    #pragma unroll
                    for (int nt = 0; nt < 6; nt++)
                        mma_bf16(acc[mt][nt], a[mt][0], a[mt][1], a[mt][2], a[mt][3],
                                 b[nt][0], b[nt][1]);
            }
        }
    }

    const int g  = lane >> 2;
    const int tq = lane & 3;
    #pragma unroll
    for (int mt = 0; mt < 2; mt++) {
        int row0 = m0 + warp_m*32 + mt*16 + g;
        int rows[2] = { row0, row0 + 8 };
        #pragma unroll
        for (int nt = 0; nt < 6; nt++) {
            int col = warp_n*48 + nt*8 + 2*tq;
            int mat = col >> 6;
            int col_in = col & 63;
            if (mat < 2) {
                int pi = col_in >> 1;
                float inv = powf(10000.f, -(float)pi * (1.f / 32.f));
                #pragma unroll
                for (int rg = 0; rg < 2; rg++) {
                    int t = rows[rg] & (T_ - 1);
                    float sn, cs;
                    sincosf((float)t * inv, &sn, &cs);
                    float a0 = acc[mt][nt][rg*2], a1 = acc[mt][nt][rg*2 + 1];
                    float v0 = a0*cs - a1*sn, v1 = a1*cs + a0*sn;
                    size_t base = (size_t)rows[rg] * H_ + col_in;
                    if (mat == 0) {
                        *reinterpret_cast<uint32_t*>(&g_Qhi[base]) = h2pack(v0, v1);
                        *reinterpret_cast<uint32_t*>(&g_Qlo[base]) =
                            h2pack(h_lo_res(v0), h_lo_res(v1));
                    } else {
                        *reinterpret_cast<uint32_t*>(&g_Khi[base]) = h2pack(v0, v1);
                    }
                }
            } else {
                #pragma unroll
                for (int rg = 0; rg < 2; rg++) {
                    int bb = rows[rg] >> 11, tt = rows[rg] & (T_ - 1);
                    #pragma unroll
                    for (int e = 0; e < 2; e++) {
                        float v = acc[mt][nt][rg*2 + e];
                        size_t idx = ((size_t)bb * H_ + (col_in + e)) * T_ + tt;
                        g_VThi[idx] = __float2half_rn(v);
                    }
                }
            }
        }
    }
}

// ---------------------------------------------------------------------------
// Split-KV attention partial: S = Qh*Kh + Ql*Kh (2 passes); PV = Ph*Vh (1 pass).
// Base-2 softmax with ex2.approx.f16x2 (P emerges packed fp16 for PV; l summed
// in fp32 over the exact fp16 p's). Double-buffered KV via cp.async.
// smem: Q hi/lo + 2x(K,V) = 6 tiles = 55296B -> 4 CTAs/SM.
// ---------------------------------------------------------------------------
#define ASTR   72
#define TILE_B (64*ASTR*2)
#define AQHI   0
#define AQLO   TILE_B
#define AKV0   (2*TILE_B)           // K, V  (buffer 0)
#define AKV1   (4*TILE_B)           // K, V  (buffer 1)
#define ASM_TOT (6*TILE_B)          // 55296

#define SCALE_L2E 0.1803368801f     // 0.125 * log2(e)
#define MASK_NEG  (-3.0e4f)

__device__ __forceinline__ void stage_kv(uint32_t sdst, int b, int kt, int tid) {
    const __half* Kh = g_Khi + ((size_t)b * T_ + kt*64) * H_;
    #pragma unroll
    for (int it = tid; it < 512; it += 128) {
        int r = it >> 3, s = it & 7;
        uint32_t off = (uint32_t)(r * (ASTR*2) + s*16);
        CP_A16(sdst + off, Kh + r*64 + s*8);
        size_t vsrc = ((size_t)b * H_ + r) * T_ + kt*64 + s*8;
        CP_A16(sdst + TILE_B + off, g_VThi + vsrc);
    }
}

__global__ __launch_bounds__(128, 4) void attn_part_kernel(float* __restrict__ out)
{
    extern __shared__ char smem[];
    const uint32_t sbase = smem_u32(smem);
    const int tid  = threadIdx.x;
    const int wid  = tid >> 5;
    const int lane = tid & 31;
    const int b    = blockIdx.y;
    const int r8   = lane & 7;
    const int mlo  = (lane >> 3) & 1;
    const int khi  = (lane >> 4) & 1;
    const int g    = lane >> 2;
    const int tq   = lane & 3;

    int qt = 0, chunk = 0;
    {
        int bx = blockIdx.x, acc = 0;
        #pragma unroll 1
        for (int q = 0; q < 32; q++) {
            int nc = (q >> 3) + 1;
            if (bx < acc + nc) { qt = q; chunk = bx - acc; break; }
            acc += nc;
        }
    }
    const int kt0 = chunk * CHUNK;
    const int kt1 = (kt0 + CHUNK - 1 < qt) ? (kt0 + CHUNK - 1) : qt;

    const uint32_t aRowOff = (uint32_t)((wid*16 + mlo*8 + r8) * (ASTR*2) + khi*16);
    uint32_t bRowOff[4];
    #pragma unroll
    for (int p = 0; p < 4; p++)
        bRowOff[p] = (uint32_t)((p*16 + khi*8 + r8) * (ASTR*2) + mlo*16);

    // stage Q + first KV tile (group 0)
    {
        const __half* Qh = g_Qhi + ((size_t)b * T_ + qt*64) * H_;
        const __half* Ql = g_Qlo + ((size_t)b * T_ + qt*64) * H_;
        #pragma unroll
        for (int it = tid; it < 512; it += 128) {
            int r = it >> 3, s = it & 7;
            uint32_t off = (uint32_t)(r * (ASTR*2) + s*16);
            CP_A16(sbase + AQHI + off, Qh + r*64 + s*8);
            CP_A16(sbase + AQLO + off, Ql + r*64 + s*8);
        }
        stage_kv(sbase + AKV0, b, kt0, tid);
        CP_COMMIT();
    }

    float m0r = MASK_NEG, m1r = MASK_NEG, l0 = 0.f, l1 = 0.f;
    float o[8][4];
    #pragma unroll
    for (int nt = 0; nt < 8; nt++)
        #pragma unroll
        for (int q = 0; q < 4; q++) o[nt][q] = 0.f;

    #pragma unroll 1
    for (int kt = kt0; kt <= kt1; kt++) {
        const uint32_t kvb = sbase + (((kt - kt0) & 1) ? AKV1 : AKV0);

        // prefetch next KV tile into the other buffer, then wait for kt's data
        if (kt < kt1) {
            stage_kv(sbase + (((kt + 1 - kt0) & 1) ? AKV1 : AKV0), b, kt + 1, tid);
            CP_COMMIT();
            CP_WAIT1();
        } else {
            CP_WAIT0();
        }
        __syncthreads();

        // ---- S = Q K^T (2 passes: Qh*Kh + Ql*Kh) ----
        float s_[8][4];
        #pragma unroll
        for (int nt = 0; nt < 8; nt++)
            #pragma unroll
            for (int q = 0; q < 4; q++) s_[nt][q] = 0.f;

        #pragma unroll
        for (int ks = 0; ks < 4; ks++) {
            uint32_t kb = (uint32_t)(ks * 32);
            uint32_t qh0, qh1, qh2, qh3, ql0, ql1, ql2, ql3;
            ldmx4(qh0, qh1, qh2, qh3, sbase + AQHI + aRowOff + kb);
            ldmx4(ql0, ql1, ql2, ql3, sbase + AQLO + aRowOff + kb);
            #pragma unroll
            for (int p = 0; p < 4; p++) {
                uint32_t kh0, kh1, kh2, kh3;
                ldmx4(kh0, kh1, kh2, kh3, kvb + bRowOff[p] + kb);
                mma_f16(s_[2*p],   qh0, qh1, qh2, qh3, kh0, kh1);
                mma_f16(s_[2*p+1], qh0, qh1, qh2, qh3, kh2, kh3);
                mma_f16(s_[2*p],   ql0, ql1, ql2, ql3, kh0, kh1);
                mma_f16(s_[2*p+1], ql0, ql1, ql2, ql3, kh2, kh3);
            }
        }

        // scale into base-2 space
        #pragma unroll
        for (int nt = 0; nt < 8; nt++)
            #pragma unroll
            for (int q = 0; q < 4; q++) s_[nt][q] *= SCALE_L2E;
        if (kt == qt) {
            int qr0 = qt*64 + wid*16 + g;
            #pragma unroll
            for (int nt = 0; nt < 8; nt++) {
                int kc0 = kt*64 + nt*8 + 2*tq;
                if (kc0     > qr0)     s_[nt][0] = MASK_NEG;
                if (kc0 + 1 > qr0)     s_[nt][1] = MASK_NEG;
                if (kc0     > qr0 + 8) s_[nt][2] = MASK_NEG;
                if (kc0 + 1 > qr0 + 8) s_[nt][3] = MASK_NEG;
            }
        }

        // ---- online softmax (base-2; p computed as packed fp16) ----
        float mx0 = MASK_NEG, mx1 = MASK_NEG;
        #pragma unroll
        for (int nt = 0; nt < 8; nt++) {
            mx0 = fmaxf(mx0, fmaxf(s_[nt][0], s_[nt][1]));
            mx1 = fmaxf(mx1, fmaxf(s_[nt][2], s_[nt][3]));
        }
        mx0 = fmaxf(mx0, __shfl_xor_sync(0xffffffffu, mx0, 1));
        mx0 = fmaxf(mx0, __shfl_xor_sync(0xffffffffu, mx0, 2));
        mx1 = fmaxf(mx1, __shfl_xor_sync(0xffffffffu, mx1, 1));
        mx1 = fmaxf(mx1, __shfl_xor_sync(0xffffffffu, mx1, 2));
        float mn0 = fmaxf(m0r, mx0), mn1 = fmaxf(m1r, mx1);
        float al0 = ex2f(m0r - mn0), al1 = ex2f(m1r - mn1);

        uint32_t pe[8][2];
        float rs0 = 0.f, rs1 = 0.f;
        #pragma unroll
        for (int nt = 0; nt < 8; nt++) {
            pe[nt][0] = ex2_h2(h2pack(s_[nt][0] - mn0, s_[nt][1] - mn0));
            pe[nt][1] = ex2_h2(h2pack(s_[nt][2] - mn1, s_[nt][3] - mn1));
            float2 f0 = h2f2(pe[nt][0]);
            float2 f1 = h2f2(pe[nt][1]);
            rs0 += f0.x + f0.y;
            rs1 += f1.x + f1.y;
        }
        rs0 += __shfl_xor_sync(0xffffffffu, rs0, 1);
        rs0 += __shfl_xor_sync(0xffffffffu, rs0, 2);
        rs1 += __shfl_xor_sync(0xffffffffu, rs1, 1);
        rs1 += __shfl_xor_sync(0xffffffffu, rs1, 2);
        l0 = l0 * al0 + rs0;  l1 = l1 * al1 + rs1;
        m0r = mn0;  m1r = mn1;
        #pragma unroll
        for (int nt = 0; nt < 8; nt++) {
            o[nt][0] *= al0; o[nt][1] *= al0;
            o[nt][2] *= al1; o[nt][3] *= al1;
        }

        // ---- O += P V  (P fragments come straight from pe) ----
        #pragma unroll
        for (int kk = 0; kk < 4; kk++) {
            uint32_t kb = (uint32_t)(kk * 32);
            #pragma unroll
            for (int p = 0; p < 4; p++) {
                uint32_t vh0, vh1, vh2, vh3;
                ldmx4(vh0, vh1, vh2, vh3, kvb + TILE_B + bRowOff[p] + kb);
                mma_f16(o[2*p],   pe[2*kk][0], pe[2*kk][1], pe[2*kk+1][0], pe[2*kk+1][1],
                        vh0, vh1);
                mma_f16(o[2*p+1], pe[2*kk][0], pe[2*kk][1], pe[2*kk+1][0], pe[2*kk+1][1],
                        vh2, vh3);
            }
        }

        __syncthreads();   // all warps done reading kt's buffer (next iter writes it)
    }

    const int row0 = wid*16 + g;
    if (qt < 8) {
        float rc0 = 1.f / l0, rc1 = 1.f / l1;
        #pragma unroll
        for (int nt = 0; nt < 8; nt++) {
            int col = nt*8 + 2*tq;
            *reinterpret_cast<float2*>(&out[((size_t)b*T_ + qt*64 + row0) * H_ + col]) =
                make_float2(o[nt][0]*rc0, o[nt][1]*rc0);
            *reinterpret_cast<float2*>(&out[((size_t)b*T_ + qt*64 + row0 + 8) * H_ + col]) =
                make_float2(o[nt][2]*rc1, o[nt][3]*rc1);
        }
    } else {
        const int part = (b*32 + qt)*4 + chunk;
        float* Op = g_Opart + (size_t)part * 64 * 64;
        #pragma unroll
        for (int nt = 0; nt < 8; nt++) {
            int col = nt*8 + 2*tq;
            *reinterpret_cast<float2*>(&Op[(row0)     * 64 + col]) = make_float2(o[nt][0], o[nt][1]);
            *reinterpret_cast<float2*>(&Op[(row0 + 8) * 64 + col]) = make_float2(o[nt][2], o[nt][3]);
        }
        if (tq == 0) {
            g_mpart[part*64 + row0]     = m0r;
            g_mpart[part*64 + row0 + 8] = m1r;
            g_lpart[part*64 + row0]     = l0;
            g_lpart[part*64 + row0 + 8] = l1;
        }
    }
}

// ---------------------------------------------------------------------------
// Merge: combine chunk partials per (b, qt) for qt >= 8 (base-2 weights).
// ---------------------------------------------------------------------------
__global__ __launch_bounds__(256) void attn_merge_kernel(float* __restrict__ out)
{
    const int qt = blockIdx.x + 8, b = blockIdx.y;
    const int nc = (qt >> 3) + 1;
    const int r  = (int)blockIdx.z * 16 + (threadIdx.x >> 4);  // 0..63
    const int cb = (threadIdx.x & 15) * 4;
    const int pbase = (b*32 + qt)*4;

    float m = -3.0e4f;
    #pragma unroll
    for (int c = 0; c < 4; c++)
        if (c < nc) m = fmaxf(m, g_mpart[(pbase + c)*64 + r]);
    float w[4];
    float l = 0.f;
    #pragma unroll
    for (int c = 0; c < 4; c++) {
        if (c < nc) {
            w[c] = ex2f(g_mpart[(pbase + c)*64 + r] - m);
            l += w[c] * g_lpart[(pbase + c)*64 + r];
        } else w[c] = 0.f;
    }
    float inv = 1.f / l;

    float4 acc = make_float4(0.f, 0.f, 0.f, 0.f);
    #pragma unroll
    for (int c = 0; c < 4; c++) {
        if (c < nc) {
            float4 v = *reinterpret_cast<const float4*>(
                &g_Opart[((size_t)(pbase + c)*64 + r)*64 + cb]);
            acc.x += w[c]*v.x; acc.y += w[c]*v.y;
            acc.z += w[c]*v.z; acc.w += w[c]*v.w;
        }
    }
    acc.x *= inv; acc.y *= inv; acc.z *= inv; acc.w *= inv;
    *reinterpret_cast<float4*>(&out[((size_t)b*T_ + qt*64 + r)*H_ + cb]) = acc;
}

extern "C" void kernel_launch(void* const* d_in, const int* in_sizes, int n_in,
                              void* d_out, int out_size)
{
    const float* x  = (const float*)d_in[0];
    const float* Wq = (const float*)d_in[1];
    const float* Wk = (const float*)d_in[2];
    const float* Wv = (const float*)d_in[3];
    float* out = (float*)d_out;

    cudaFuncSetAttribute(proj_gemm_kernel,
                         cudaFuncAttributeMaxDynamicSharedMemorySize, SM_TOT);
    cudaFuncSetAttribute(attn_part_kernel,
                         cudaFuncAttributeMaxDynamicSharedMemorySize, ASM_TOT);

    prep_B_kernel<<<(192 * 1024) / 256, 256>>>(Wq, Wk, Wv);
    proj_gemm_kernel<<<(B_ * T_) / 128, 512, SM_TOT>>>(x);
    attn_part_kernel<<<dim3(80, B_), 128, ASM_TOT>>>(out);
    attn_merge_kernel<<<dim3(24, B_, 4), 256>>>(out);
}